// round 1
// baseline (speedup 1.0000x reference)
#include <cuda_runtime.h>
#include <math.h>

// Problem constants
constexpr int Bd  = 4;
constexpr int S1  = 64;
constexpr int S2  = 256;
constexpr int D   = 256;
constexpr int Hh  = 8;
constexpr int HD  = 32;
constexpr int Fd  = 1024;
constexpr int TOK = Bd * S1 * S2;       // 65536 tokens

// Scratch (device globals; allocation-free kernel_launch)
__device__ float g_q [TOK * D];
__device__ float g_k [TOK * D];
__device__ float g_v [TOK * D];
__device__ float g_ao[TOK * D];
__device__ float g_s [TOK * D];
__device__ float g_h [TOK * D];
__device__ float g_ff[TOK * Fd];

// ---------------------------------------------------------------------------
// Tiled SGEMM: C[M,N] = epi( A[M,K] @ B[K,N] + bias , resid )
// BM=128, BN=64, BK=16, 256 threads, 8x4 per-thread tile.
// CONV3: A is gathered from x with time-conv taps (K = 3*D, tap offset -1..1,
//        zero outside [0,S2) in the time axis; time = row % S2).
// EPI: 0 = +bias ; 1 = +bias +resid ; 2 = +bias, leaky-relu(0.01)
// ---------------------------------------------------------------------------
template<bool CONV3, int EPI>
__global__ __launch_bounds__(256)
void gemm_k(const float* __restrict__ A, const float* __restrict__ B,
            const float* __restrict__ bias, const float* __restrict__ R,
            float* __restrict__ C, int M, int N, int K)
{
    __shared__ float As[16][132];   // [k][m], padded
    __shared__ float Bs[16][68];    // [k][n], padded

    const int tid = threadIdx.x;
    const int tx  = tid & 15;       // 0..15 -> 4 output cols
    const int ty  = tid >> 4;       // 0..15 -> 8 output rows
    const int m0  = blockIdx.y * 128;
    const int n0  = blockIdx.x * 64;

    // A-load mapping: thread owns k-slot (tid&15), rows (tid>>4) + 16*i
    const int ka = tid & 15;
    const int ma = tid >> 4;
    // B-load mapping: k-slot tid>>4, 4 cols (tid&15)*4
    const int kb = tid >> 4;
    const int nb = (tid & 15) * 4;

    float acc[8][4];
#pragma unroll
    for (int i = 0; i < 8; i++)
#pragma unroll
        for (int j = 0; j < 4; j++) acc[i][j] = 0.f;

    for (int kt = 0; kt < K; kt += 16) {
        // load A tile (gathered for conv)
#pragma unroll
        for (int i = 0; i < 8; i++) {
            const int m = m0 + ma + i * 16;
            float val;
            if (CONV3) {
                const int kk = kt + ka;
                const int tp = kk >> 8;          // tap 0..2
                const int dd = kk & 255;         // input channel
                const int of = tp - 1;           // time offset -1..1
                const int t  = m & (S2 - 1);
                const int ts = t + of;
                val = ((unsigned)ts < (unsigned)S2) ? A[(long long)(m + of) * D + dd] : 0.f;
            } else {
                val = A[(long long)m * K + kt + ka];
            }
            As[ka][ma + i * 16] = val;
        }
        // load B tile
        {
            const float4 bv = *(const float4*)&B[(long long)(kt + kb) * N + n0 + nb];
            *(float4*)&Bs[kb][nb] = bv;
        }
        __syncthreads();

#pragma unroll
        for (int k = 0; k < 16; k++) {
            const float4 a0 = *(const float4*)&As[k][ty * 8];
            const float4 a1 = *(const float4*)&As[k][ty * 8 + 4];
            const float4 b4 = *(const float4*)&Bs[k][tx * 4];
            const float a[8] = {a0.x, a0.y, a0.z, a0.w, a1.x, a1.y, a1.z, a1.w};
            const float b[4] = {b4.x, b4.y, b4.z, b4.w};
#pragma unroll
            for (int i = 0; i < 8; i++)
#pragma unroll
                for (int j = 0; j < 4; j++)
                    acc[i][j] += a[i] * b[j];
        }
        __syncthreads();
    }

    // epilogue
    const float4 bi = *(const float4*)&bias[n0 + tx * 4];
#pragma unroll
    for (int i = 0; i < 8; i++) {
        const int row = m0 + ty * 8 + i;
        float4 o;
        o.x = acc[i][0] + bi.x;
        o.y = acc[i][1] + bi.y;
        o.z = acc[i][2] + bi.z;
        o.w = acc[i][3] + bi.w;
        if (EPI == 1) {
            const float4 r4 = *(const float4*)&R[(long long)row * N + n0 + tx * 4];
            o.x += r4.x; o.y += r4.y; o.z += r4.z; o.w += r4.w;
        }
        if (EPI == 2) {
            o.x = o.x > 0.f ? o.x : 0.01f * o.x;
            o.y = o.y > 0.f ? o.y : 0.01f * o.y;
            o.z = o.z > 0.f ? o.z : 0.01f * o.z;
            o.w = o.w > 0.f ? o.w : 0.01f * o.w;
        }
        *(float4*)&C[(long long)row * N + n0 + tx * 4] = o;
    }
}

// ---------------------------------------------------------------------------
// Attention: one block per (b, n, h). 256 threads, one query row each.
// K/V tiles (256x32 fp32 each) in dynamic smem; 2-pass online softmax
// (recompute scores in pass 2 instead of storing the 256x256 tile).
// ---------------------------------------------------------------------------
__global__ __launch_bounds__(256)
void attn_k(const float* __restrict__ q, const float* __restrict__ k,
            const float* __restrict__ v, float* __restrict__ o)
{
    extern __shared__ float sm[];
    float* ks = sm;                 // [S2][HD]
    float* vs = sm + S2 * HD;

    const int bid = blockIdx.x;
    const int h   = bid & (Hh - 1);
    const int bn  = bid >> 3;                        // b*S1 + n
    const long long base = (long long)bn * S2 * D + h * HD;
    const int tid = threadIdx.x;

    for (int e = tid; e < S2 * HD; e += 256) {
        const int s = e >> 5, d = e & 31;
        ks[e] = k[base + (long long)s * D + d];
        vs[e] = v[base + (long long)s * D + d];
    }
    float qr[32];
#pragma unroll
    for (int j = 0; j < 8; j++) {
        const float4 t4 = *(const float4*)&q[base + (long long)tid * D + j * 4];
        qr[j * 4 + 0] = t4.x; qr[j * 4 + 1] = t4.y;
        qr[j * 4 + 2] = t4.z; qr[j * 4 + 3] = t4.w;
    }
    __syncthreads();

    const float scale = 0.17677669529663687f;  // 1/sqrt(32)

    float mmax = -1e30f;
    for (int s = 0; s < S2; s++) {
        float dot = 0.f;
#pragma unroll
        for (int d = 0; d < 32; d++) dot += qr[d] * ks[s * 32 + d];
        mmax = fmaxf(mmax, dot * scale);
    }

    float sum = 0.f;
    float oa[32];
#pragma unroll
    for (int d = 0; d < 32; d++) oa[d] = 0.f;

    for (int s = 0; s < S2; s++) {
        float dot = 0.f;
#pragma unroll
        for (int d = 0; d < 32; d++) dot += qr[d] * ks[s * 32 + d];
        const float p = __expf(dot * scale - mmax);
        sum += p;
#pragma unroll
        for (int d = 0; d < 32; d++) oa[d] += p * vs[s * 32 + d];
    }

    const float inv = 1.f / sum;
#pragma unroll
    for (int j = 0; j < 8; j++) {
        float4 t4;
        t4.x = oa[j * 4 + 0] * inv; t4.y = oa[j * 4 + 1] * inv;
        t4.z = oa[j * 4 + 2] * inv; t4.w = oa[j * 4 + 3] * inv;
        *(float4*)&o[base + (long long)tid * D + j * 4] = t4;
    }
}

// ---------------------------------------------------------------------------
// LayerNorm over last dim (256). One warp per row, 8 rows/block.
// ---------------------------------------------------------------------------
__global__ __launch_bounds__(256)
void ln_k(const float* __restrict__ X, const float* __restrict__ g,
          const float* __restrict__ be, float* __restrict__ Y)
{
    const int r    = blockIdx.x * 8 + (threadIdx.x >> 5);
    const int lane = threadIdx.x & 31;
    const float* xr = X + (long long)r * D;

    float xv[8];
    float s = 0.f, ss = 0.f;
#pragma unroll
    for (int j = 0; j < 8; j++) {
        const float t = xr[lane + j * 32];
        xv[j] = t; s += t; ss += t * t;
    }
#pragma unroll
    for (int ofs = 16; ofs > 0; ofs >>= 1) {
        s  += __shfl_xor_sync(0xffffffffu, s,  ofs);
        ss += __shfl_xor_sync(0xffffffffu, ss, ofs);
    }
    const float mu  = s * (1.f / 256.f);
    const float var = ss * (1.f / 256.f) - mu * mu;
    const float rs  = rsqrtf(var + 1e-5f);

    float* yr = Y + (long long)r * D;
#pragma unroll
    for (int j = 0; j < 8; j++) {
        const int d = lane + j * 32;
        yr[d] = (xv[j] - mu) * rs * g[d] + be[d];
    }
}

// ---------------------------------------------------------------------------
extern "C" void kernel_launch(void* const* d_in, const int* in_sizes, int n_in,
                              void* d_out, int out_size)
{
    const float* x   = (const float*)d_in[0];
    const float* Wq  = (const float*)d_in[1];
    const float* bq  = (const float*)d_in[2];
    const float* Wk  = (const float*)d_in[3];
    const float* bk  = (const float*)d_in[4];
    const float* Wv  = (const float*)d_in[5];
    const float* bv  = (const float*)d_in[6];
    const float* Wo  = (const float*)d_in[7];
    const float* bo  = (const float*)d_in[8];
    const float* W1  = (const float*)d_in[9];
    const float* b1  = (const float*)d_in[10];
    const float* W2  = (const float*)d_in[11];
    const float* b2  = (const float*)d_in[12];
    const float* g1  = (const float*)d_in[13];
    const float* be1 = (const float*)d_in[14];
    const float* g2  = (const float*)d_in[15];
    const float* be2 = (const float*)d_in[16];
    float* out = (float*)d_out;

    float *q, *k, *v, *ao, *sbuf, *h, *ff;
    cudaGetSymbolAddress((void**)&q,    g_q);
    cudaGetSymbolAddress((void**)&k,    g_k);
    cudaGetSymbolAddress((void**)&v,    g_v);
    cudaGetSymbolAddress((void**)&ao,   g_ao);
    cudaGetSymbolAddress((void**)&sbuf, g_s);
    cudaGetSymbolAddress((void**)&h,    g_h);
    cudaGetSymbolAddress((void**)&ff,   g_ff);

    cudaFuncSetAttribute(attn_k, cudaFuncAttributeMaxDynamicSharedMemorySize, 2 * S2 * HD * 4);

    const dim3 gD(D  / 64, TOK / 128);   // N=256  GEMMs
    const dim3 gF(Fd / 64, TOK / 128);   // N=1024 GEMM

    // Q = conv(x, Wq) + bq ; K = conv(x, Wk) + bk  (as gathered GEMM, K=768)
    gemm_k<true , 0><<<gD, 256>>>(x, Wq, bq, nullptr, q, TOK, D, 3 * D);
    gemm_k<true , 0><<<gD, 256>>>(x, Wk, bk, nullptr, k, TOK, D, 3 * D);
    // V = x @ Wv + bv
    gemm_k<false, 0><<<gD, 256>>>(x, Wv, bv, nullptr, v, TOK, D, D);
    // attention per (b, n, h)
    attn_k<<<Bd * S1 * Hh, 256, 2 * S2 * HD * 4>>>(q, k, v, ao);
    // s = x + ao @ Wo + bo ; h = LN1(s)
    gemm_k<false, 1><<<gD, 256>>>(ao, Wo, bo, x, sbuf, TOK, D, D);
    ln_k<<<TOK / 8, 256>>>(sbuf, g1, be1, h);
    // ff = leaky(h @ W1 + b1) ; s = h + ff @ W2 + b2 ; out = LN2(s)
    gemm_k<false, 2><<<gF, 256>>>(h, W1, b1, nullptr, ff, TOK, Fd, D);
    gemm_k<false, 1><<<gD, 256>>>(ff, W2, b2, h, sbuf, TOK, D, Fd);
    ln_k<<<TOK / 8, 256>>>(sbuf, g2, be2, out);
}

// round 3
// speedup vs baseline: 1.8808x; 1.8808x over previous
#include <cuda_runtime.h>
#include <cuda_bf16.h>
#include <cstdint>
#include <math.h>

using bf16 = __nv_bfloat16;

// ---------------- problem constants ----------------
constexpr int Bd  = 4;
constexpr int S1  = 64;
constexpr int S2  = 256;
constexpr int D   = 256;
constexpr int Hh  = 8;
constexpr int HD  = 32;
constexpr int Fd  = 1024;
constexpr int TOK = Bd * S1 * S2;     // 65536
constexpr int BN_ = Bd * S1;          // 256 (b,n) groups
constexpr int SP  = S2 + 2;           // padded time length 258

// ---------------- scratch (device globals) ----------------
__device__ bf16  g_xph[BN_ * SP * D];
__device__ bf16  g_xpl[BN_ * SP * D];
__device__ float g_q  [TOK * D];
__device__ float g_k  [TOK * D];
__device__ float g_v  [TOK * D];
__device__ bf16  g_aoh[TOK * D];
__device__ bf16  g_aol[TOK * D];
__device__ float g_s  [TOK * D];
__device__ float g_h  [TOK * D];
__device__ bf16  g_hh [TOK * D];
__device__ bf16  g_hl [TOK * D];
__device__ bf16  g_ffh[TOK * Fd];
__device__ bf16  g_ffl[TOK * Fd];
// transposed weights, hi/lo
__device__ bf16 g_wqh[D * 3 * D], g_wql[D * 3 * D];
__device__ bf16 g_wkh[D * 3 * D], g_wkl[D * 3 * D];
__device__ bf16 g_wvh[D * D],     g_wvl[D * D];
__device__ bf16 g_woh[D * D],     g_wol[D * D];
__device__ bf16 g_w1h[Fd * D],    g_w1l[Fd * D];
__device__ bf16 g_w2h[D * Fd],    g_w2l[D * Fd];

// ---------------- helpers ----------------
__device__ __forceinline__ uint32_t smem_to_u32(const void* p) {
    uint32_t a;
    asm("{ .reg .u64 t; cvta.to.shared.u64 t, %1; cvt.u32.u64 %0, t; }" : "=r"(a) : "l"(p));
    return a;
}
#define CP_ASYNC16(s, g) \
    asm volatile("cp.async.cg.shared.global [%0], [%1], 16;" :: "r"((uint32_t)(s)), "l"(g))
#define CP_ASYNC_COMMIT() asm volatile("cp.async.commit_group;" ::: "memory")
#define SW128(o) ((o) ^ (((o) >> 3) & 0x70))

__device__ __forceinline__ void ldsm4(uint32_t addr, uint32_t& r0, uint32_t& r1,
                                      uint32_t& r2, uint32_t& r3) {
    asm volatile("ldmatrix.sync.aligned.m8n8.x4.shared.b16 {%0,%1,%2,%3}, [%4];"
                 : "=r"(r0), "=r"(r1), "=r"(r2), "=r"(r3) : "r"(addr));
}
__device__ __forceinline__ void mma_bf16(float* c, const uint32_t* a, const uint32_t* b) {
    asm volatile("mma.sync.aligned.m16n8k16.row.col.f32.bf16.bf16.f32 "
                 "{%0,%1,%2,%3}, {%4,%5,%6,%7}, {%8,%9}, {%0,%1,%2,%3};"
                 : "+f"(c[0]), "+f"(c[1]), "+f"(c[2]), "+f"(c[3])
                 : "r"(a[0]), "r"(a[1]), "r"(a[2]), "r"(a[3]), "r"(b[0]), "r"(b[1]));
}
__device__ __forceinline__ void split_bf16(float v, bf16& h, bf16& l) {
    h = __float2bfloat16(v);
    l = __float2bfloat16(v - __bfloat162float(h));
}

// ---------------------------------------------------------------------------
// Tensor-core GEMM via mma.sync bf16, 128x128 block tile, BK=64, split-bf16
// (3 accumulating passes: Ah*Bh + Ah*Bl + Al*Bh), cp.async double buffering.
// A: [rows][ldA] bf16 hi/lo (CONV: padded-time addressing, ntaps segments)
// B: [N][ldB]    bf16 hi/lo (K-major; tap segment t at col offset t*Ktap)
// EPI: 0 = bias -> Cf fp32 ; 1 = bias+R -> Cf fp32 ; 2 = bias+leaky -> Ch/Cl bf16
// smem: stage s at s*65536: [A_hi 16K][A_lo 16K][B_hi 16K][B_lo 16K]
// ---------------------------------------------------------------------------
template<int EPI, bool CONV>
__global__ __launch_bounds__(256)
void gemm_tc(const bf16* __restrict__ Ah, const bf16* __restrict__ Al, int ldA,
             const bf16* __restrict__ Bh, const bf16* __restrict__ Bl, int ldB,
             int Ktap, int ntaps, int tapbase,
             const float* __restrict__ bias, const float* __restrict__ R,
             float* __restrict__ Cf, bf16* __restrict__ Ch, bf16* __restrict__ Cl,
             int Nt)
{
    extern __shared__ char smem[];
    const uint32_t sbase = smem_to_u32(smem);
    const int tid = threadIdx.x, wid = tid >> 5, lane = tid & 31;
    const int m0 = blockIdx.y * 128, n0 = blockIdx.x * 128;

    int rowbase;
    if (CONV) { const int bn = m0 >> 8; const int t0 = m0 & 255; rowbase = bn * SP + t0 + tapbase; }
    else      { rowbase = m0; }

    const int kcpt = Ktap >> 6;          // 64-wide K chunks per tap
    const int nch  = ntaps * kcpt;
    const int c16  = tid & 7;

    auto load_chunk = [&](int c, int stage) {
        const int tap = c / kcpt;
        const int kt  = (c - tap * kcpt) << 6;
        const size_t aoff = (size_t)(rowbase + tap) * ldA + kt + c16 * 8;
        const size_t boff = (size_t)n0 * ldB + (size_t)tap * Ktap + kt + c16 * 8;
        const uint32_t st = sbase + stage * 65536;
#pragma unroll
        for (int i = 0; i < 4; i++) {
            const int row = (tid >> 3) + i * 32;
            const uint32_t so = SW128((uint32_t)(row * 128 + c16 * 16));
            CP_ASYNC16(st +         so, Ah + aoff + (size_t)row * ldA);
            CP_ASYNC16(st + 16384 + so, Al + aoff + (size_t)row * ldA);
            CP_ASYNC16(st + 32768 + so, Bh + boff + (size_t)row * ldB);
            CP_ASYNC16(st + 49152 + so, Bl + boff + (size_t)row * ldB);
        }
        CP_ASYNC_COMMIT();
    };

    load_chunk(0, 0);
    load_chunk(1, 1);

    // per-thread fragment addressing
    const int wm  = wid & 1,  wn  = wid >> 1;
    const int m0w = wm * 64,  n0w = wn * 32;
    const int tq  = lane >> 3, rin = lane & 7;
    const int aRow = m0w + (tq & 1) * 8 + rin;    // + mt*16
    const int akh  = tq >> 1;                     // k-half for A tiles
    const int bRow = n0w + (tq >> 1) * 8 + rin;   // + nt2*16
    const int bkh  = tq & 1;                      // k-half for B tiles

    float acc[4][4][4];
#pragma unroll
    for (int i = 0; i < 4; i++)
#pragma unroll
        for (int j = 0; j < 4; j++)
#pragma unroll
            for (int r = 0; r < 4; r++) acc[i][j][r] = 0.f;

    for (int c = 0; c < nch; c++) {
        if (c + 1 < nch) asm volatile("cp.async.wait_group 1;" ::: "memory");
        else             asm volatile("cp.async.wait_group 0;" ::: "memory");
        __syncthreads();

        const uint32_t Ab = sbase + (c & 1) * 65536;
        const uint32_t Bb = Ab + 32768;

#pragma unroll
        for (int ks = 0; ks < 4; ks++) {
            uint32_t ah[4][4], al[4][4], bh[4][2], bl[4][2];
#pragma unroll
            for (int mt = 0; mt < 4; mt++) {
                const uint32_t ad = Ab + (uint32_t)((aRow + mt * 16) * 128)
                                  + (uint32_t)(((ks * 2 + akh) ^ rin) << 4);
                ldsm4(ad,          ah[mt][0], ah[mt][1], ah[mt][2], ah[mt][3]);
                ldsm4(ad + 16384,  al[mt][0], al[mt][1], al[mt][2], al[mt][3]);
            }
#pragma unroll
            for (int nt2 = 0; nt2 < 2; nt2++) {
                const uint32_t bd = Bb + (uint32_t)((bRow + nt2 * 16) * 128)
                                  + (uint32_t)(((ks * 2 + bkh) ^ rin) << 4);
                uint32_t r0, r1, r2, r3;
                ldsm4(bd, r0, r1, r2, r3);
                bh[nt2 * 2][0] = r0; bh[nt2 * 2][1] = r1;
                bh[nt2 * 2 + 1][0] = r2; bh[nt2 * 2 + 1][1] = r3;
                ldsm4(bd + 16384, r0, r1, r2, r3);
                bl[nt2 * 2][0] = r0; bl[nt2 * 2][1] = r1;
                bl[nt2 * 2 + 1][0] = r2; bl[nt2 * 2 + 1][1] = r3;
            }
#pragma unroll
            for (int mt = 0; mt < 4; mt++)
#pragma unroll
                for (int nt = 0; nt < 4; nt++) {
                    mma_bf16(acc[mt][nt], ah[mt], bh[nt]);
                    mma_bf16(acc[mt][nt], ah[mt], bl[nt]);
                    mma_bf16(acc[mt][nt], al[mt], bh[nt]);
                }
        }
        __syncthreads();
        if (c + 2 < nch) load_chunk(c + 2, c & 1);
    }

    // ---------------- epilogue (from registers) ----------------
    const int erow = lane >> 2;             // 0..7
    const int ecol = (lane & 3) * 2;        // 0,2,4,6
#pragma unroll
    for (int mt = 0; mt < 4; mt++) {
#pragma unroll
        for (int nt = 0; nt < 4; nt++) {
            const int col = n0 + n0w + nt * 8 + ecol;
            const float2 bi = *(const float2*)&bias[col];
#pragma unroll
            for (int half = 0; half < 2; half++) {
                const int row = m0 + m0w + mt * 16 + erow + half * 8;
                float v0 = acc[mt][nt][half * 2 + 0] + bi.x;
                float v1 = acc[mt][nt][half * 2 + 1] + bi.y;
                if (EPI == 1) {
                    const float2 rr = *(const float2*)&R[(size_t)row * Nt + col];
                    v0 += rr.x; v1 += rr.y;
                }
                if (EPI == 2) {
                    v0 = v0 > 0.f ? v0 : 0.01f * v0;
                    v1 = v1 > 0.f ? v1 : 0.01f * v1;
                    bf16 h0, l0, h1, l1;
                    split_bf16(v0, h0, l0); split_bf16(v1, h1, l1);
                    __nv_bfloat162 hp; hp.x = h0; hp.y = h1;
                    __nv_bfloat162 lp; lp.x = l0; lp.y = l1;
                    *(__nv_bfloat162*)&Ch[(size_t)row * Nt + col] = hp;
                    *(__nv_bfloat162*)&Cl[(size_t)row * Nt + col] = lp;
                } else {
                    float2 o; o.x = v0; o.y = v1;
                    *(float2*)&Cf[(size_t)row * Nt + col] = o;
                }
            }
        }
    }
}

// ---------------------------------------------------------------------------
// pad + split x into bf16 hi/lo padded buffer [bn][258][256]
// ---------------------------------------------------------------------------
__global__ __launch_bounds__(256)
void padcvt_x(const float* __restrict__ x, bf16* __restrict__ xh, bf16* __restrict__ xl)
{
    const size_t i = (size_t)blockIdx.x * 256 + threadIdx.x;
    const int d = (int)(i & 255);
    const size_t rest = i >> 8;
    const int t = (int)(rest % SP);
    const size_t bn = rest / SP;
    float v = 0.f;
    if (t >= 1 && t <= S2) v = x[(bn * S2 + (t - 1)) * D + d];
    bf16 h, l; split_bf16(v, h, l);
    xh[i] = h; xl[i] = l;
}

// ---------------------------------------------------------------------------
// transpose + split weights: W[K][N] fp32 -> B[N][K] bf16 hi/lo
// ---------------------------------------------------------------------------
__global__ __launch_bounds__(256)
void wtcvt(const float* __restrict__ W, int K, int N, bf16* __restrict__ Bh, bf16* __restrict__ Bl)
{
    __shared__ float ts[32][33];
    const int n0 = blockIdx.x * 32, k0 = blockIdx.y * 32;
    const int tx = threadIdx.x, ty = threadIdx.y;   // 32 x 8
#pragma unroll
    for (int j = 0; j < 4; j++)
        ts[ty + j * 8][tx] = W[(size_t)(k0 + ty + j * 8) * N + n0 + tx];
    __syncthreads();
#pragma unroll
    for (int j = 0; j < 4; j++) {
        const float v = ts[tx][ty + j * 8];
        bf16 h, l; split_bf16(v, h, l);
        const size_t o = (size_t)(n0 + ty + j * 8) * K + k0 + tx;
        Bh[o] = h; Bl[o] = l;
    }
}

// ---------------------------------------------------------------------------
// Attention: one block per (b,n,h), 256 threads = one query row each.
// float4 smem reads; outputs bf16 hi/lo.
// ---------------------------------------------------------------------------
__global__ __launch_bounds__(256)
void attn_k(const float* __restrict__ q, const float* __restrict__ k,
            const float* __restrict__ v, bf16* __restrict__ oh, bf16* __restrict__ ol)
{
    extern __shared__ float sm[];
    float* ks = sm;
    float* vs = sm + S2 * HD;

    const int bid = blockIdx.x;
    const int h   = bid & (Hh - 1);
    const int bn  = bid >> 3;
    const long long base = (long long)bn * S2 * D + h * HD;
    const int tid = threadIdx.x;

    for (int e = tid; e < S2 * HD / 4; e += 256) {
        const int s = e >> 3, d4 = e & 7;
        *(float4*)&ks[s * 32 + d4 * 4] = *(const float4*)&k[base + (long long)s * D + d4 * 4];
        *(float4*)&vs[s * 32 + d4 * 4] = *(const float4*)&v[base + (long long)s * D + d4 * 4];
    }
    float4 qr[8];
#pragma unroll
    for (int j = 0; j < 8; j++)
        qr[j] = *(const float4*)&q[base + (long long)tid * D + j * 4];
    __syncthreads();

    const float scale = 0.17677669529663687f;  // 1/sqrt(32)

    float mmax = -1e30f;
    for (int s = 0; s < S2; s++) {
        float dot = 0.f;
#pragma unroll
        for (int j = 0; j < 8; j++) {
            const float4 kk = *(const float4*)&ks[s * 32 + j * 4];
            dot += qr[j].x * kk.x + qr[j].y * kk.y + qr[j].z * kk.z + qr[j].w * kk.w;
        }
        mmax = fmaxf(mmax, dot * scale);
    }

    float sum = 0.f;
    float4 oa[8];
#pragma unroll
    for (int j = 0; j < 8; j++) oa[j] = make_float4(0.f, 0.f, 0.f, 0.f);

    for (int s = 0; s < S2; s++) {
        float dot = 0.f;
#pragma unroll
        for (int j = 0; j < 8; j++) {
            const float4 kk = *(const float4*)&ks[s * 32 + j * 4];
            dot += qr[j].x * kk.x + qr[j].y * kk.y + qr[j].z * kk.z + qr[j].w * kk.w;
        }
        const float p = __expf(dot * scale - mmax);
        sum += p;
#pragma unroll
        for (int j = 0; j < 8; j++) {
            const float4 vv = *(const float4*)&vs[s * 32 + j * 4];
            oa[j].x += p * vv.x; oa[j].y += p * vv.y; oa[j].z += p * vv.z; oa[j].w += p * vv.w;
        }
    }

    const float inv = 1.f / sum;
#pragma unroll
    for (int j = 0; j < 8; j++) {
        const float vals[4] = { oa[j].x * inv, oa[j].y * inv, oa[j].z * inv, oa[j].w * inv };
#pragma unroll
        for (int p2 = 0; p2 < 2; p2++) {
            bf16 h0, l0, h1, l1;
            split_bf16(vals[p2 * 2 + 0], h0, l0);
            split_bf16(vals[p2 * 2 + 1], h1, l1);
            __nv_bfloat162 hp; hp.x = h0; hp.y = h1;
            __nv_bfloat162 lp; lp.x = l0; lp.y = l1;
            const long long o = base + (long long)tid * D + j * 4 + p2 * 2;
            *(__nv_bfloat162*)&oh[o] = hp;
            *(__nv_bfloat162*)&ol[o] = lp;
        }
    }
}

// ---------------------------------------------------------------------------
// LayerNorm (D=256). Optionally emits bf16 hi/lo of the normalized output.
// ---------------------------------------------------------------------------
template<bool EMIT>
__global__ __launch_bounds__(256)
void ln_k(const float* __restrict__ X, const float* __restrict__ g,
          const float* __restrict__ be, float* __restrict__ Y,
          bf16* __restrict__ Yh, bf16* __restrict__ Yl)
{
    const int r    = blockIdx.x * 8 + (threadIdx.x >> 5);
    const int lane = threadIdx.x & 31;
    const float* xr = X + (long long)r * D;

    float xv[8];
    float s = 0.f, ss = 0.f;
#pragma unroll
    for (int j = 0; j < 8; j++) {
        const float t = xr[lane + j * 32];
        xv[j] = t; s += t; ss += t * t;
    }
#pragma unroll
    for (int ofs = 16; ofs > 0; ofs >>= 1) {
        s  += __shfl_xor_sync(0xffffffffu, s,  ofs);
        ss += __shfl_xor_sync(0xffffffffu, ss, ofs);
    }
    const float mu  = s * (1.f / 256.f);
    const float var = ss * (1.f / 256.f) - mu * mu;
    const float rs  = rsqrtf(var + 1e-5f);

#pragma unroll
    for (int j = 0; j < 8; j++) {
        const int d = lane + j * 32;
        const float y = (xv[j] - mu) * rs * g[d] + be[d];
        Y[(long long)r * D + d] = y;
        if (EMIT) {
            bf16 h, l; split_bf16(y, h, l);
            Yh[(long long)r * D + d] = h;
            Yl[(long long)r * D + d] = l;
        }
    }
}

// ---------------------------------------------------------------------------
extern "C" void kernel_launch(void* const* d_in, const int* in_sizes, int n_in,
                              void* d_out, int out_size)
{
    const float* x   = (const float*)d_in[0];
    const float* Wq  = (const float*)d_in[1];
    const float* bq  = (const float*)d_in[2];
    const float* Wk  = (const float*)d_in[3];
    const float* bk  = (const float*)d_in[4];
    const float* Wv  = (const float*)d_in[5];
    const float* bv  = (const float*)d_in[6];
    const float* Wo  = (const float*)d_in[7];
    const float* bo  = (const float*)d_in[8];
    const float* W1  = (const float*)d_in[9];
    const float* b1  = (const float*)d_in[10];
    const float* W2  = (const float*)d_in[11];
    const float* b2  = (const float*)d_in[12];
    const float* g1  = (const float*)d_in[13];
    const float* be1 = (const float*)d_in[14];
    const float* g2  = (const float*)d_in[15];
    const float* be2 = (const float*)d_in[16];
    float* out = (float*)d_out;

    bf16 *xph, *xpl, *aoh, *aol, *hh, *hl, *ffh, *ffl;
    bf16 *wqh, *wql, *wkh, *wkl, *wvh, *wvl, *woh, *wol, *w1h, *w1l, *w2h, *w2l;
    float *q, *k, *v, *sb, *hbuf;
    cudaGetSymbolAddress((void**)&xph, g_xph); cudaGetSymbolAddress((void**)&xpl, g_xpl);
    cudaGetSymbolAddress((void**)&q,   g_q);   cudaGetSymbolAddress((void**)&k,   g_k);
    cudaGetSymbolAddress((void**)&v,   g_v);
    cudaGetSymbolAddress((void**)&aoh, g_aoh); cudaGetSymbolAddress((void**)&aol, g_aol);
    cudaGetSymbolAddress((void**)&sb,  g_s);   cudaGetSymbolAddress((void**)&hbuf, g_h);
    cudaGetSymbolAddress((void**)&hh,  g_hh);  cudaGetSymbolAddress((void**)&hl,  g_hl);
    cudaGetSymbolAddress((void**)&ffh, g_ffh); cudaGetSymbolAddress((void**)&ffl, g_ffl);
    cudaGetSymbolAddress((void**)&wqh, g_wqh); cudaGetSymbolAddress((void**)&wql, g_wql);
    cudaGetSymbolAddress((void**)&wkh, g_wkh); cudaGetSymbolAddress((void**)&wkl, g_wkl);
    cudaGetSymbolAddress((void**)&wvh, g_wvh); cudaGetSymbolAddress((void**)&wvl, g_wvl);
    cudaGetSymbolAddress((void**)&woh, g_woh); cudaGetSymbolAddress((void**)&wol, g_wol);
    cudaGetSymbolAddress((void**)&w1h, g_w1h); cudaGetSymbolAddress((void**)&w1l, g_w1l);
    cudaGetSymbolAddress((void**)&w2h, g_w2h); cudaGetSymbolAddress((void**)&w2l, g_w2l);

    constexpr int GSMEM = 2 * 65536;   // 131072: 2 stages x (A hi/lo + B hi/lo)
    cudaFuncSetAttribute(gemm_tc<0, true>,  cudaFuncAttributeMaxDynamicSharedMemorySize, GSMEM);
    cudaFuncSetAttribute(gemm_tc<1, false>, cudaFuncAttributeMaxDynamicSharedMemorySize, GSMEM);
    cudaFuncSetAttribute(gemm_tc<2, false>, cudaFuncAttributeMaxDynamicSharedMemorySize, GSMEM);
    cudaFuncSetAttribute(attn_k, cudaFuncAttributeMaxDynamicSharedMemorySize, 2 * S2 * HD * 4);

    // conversions
    padcvt_x<<<(BN_ * SP * D) / 256, 256>>>(x, xph, xpl);
    wtcvt<<<dim3(D / 32, 3 * D / 32), dim3(32, 8)>>>(Wq, 3 * D, D, wqh, wql);
    wtcvt<<<dim3(D / 32, 3 * D / 32), dim3(32, 8)>>>(Wk, 3 * D, D, wkh, wkl);
    wtcvt<<<dim3(D / 32, D / 32),     dim3(32, 8)>>>(Wv, D, D, wvh, wvl);
    wtcvt<<<dim3(D / 32, D / 32),     dim3(32, 8)>>>(Wo, D, D, woh, wol);
    wtcvt<<<dim3(Fd / 32, D / 32),    dim3(32, 8)>>>(W1, D, Fd, w1h, w1l);
    wtcvt<<<dim3(D / 32, Fd / 32),    dim3(32, 8)>>>(W2, Fd, D, w2h, w2l);

    const dim3 gD(D / 128,  TOK / 128);   // (2, 512)
    const dim3 gF(Fd / 128, TOK / 128);   // (8, 512)

    // Q, K (3-tap conv as 3 accumulated K-segments), V (tapbase=1: center tap)
    gemm_tc<0, true><<<gD, 256, GSMEM>>>(xph, xpl, D, wqh, wql, 3 * D, D, 3, 0, bq, nullptr, q, nullptr, nullptr, D);
    gemm_tc<0, true><<<gD, 256, GSMEM>>>(xph, xpl, D, wkh, wkl, 3 * D, D, 3, 0, bk, nullptr, k, nullptr, nullptr, D);
    gemm_tc<0, true><<<gD, 256, GSMEM>>>(xph, xpl, D, wvh, wvl, D,     D, 1, 1, bv, nullptr, v, nullptr, nullptr, D);
    // attention
    attn_k<<<Bd * S1 * Hh, 256, 2 * S2 * HD * 4>>>(q, k, v, aoh, aol);
    // s = x + ao@Wo + bo ; h = LN1(s)
    gemm_tc<1, false><<<gD, 256, GSMEM>>>(aoh, aol, D, woh, wol, D, D, 1, 0, bo, x, sb, nullptr, nullptr, D);
    ln_k<true><<<TOK / 8, 256>>>(sb, g1, be1, hbuf, hh, hl);
    // ff = leaky(h@W1 + b1) ; s = h + ff@W2 + b2 ; out = LN2(s)
    gemm_tc<2, false><<<gF, 256, GSMEM>>>(hh, hl, D, w1h, w1l, D, D, 1, 0, b1, nullptr, nullptr, ffh, ffl, Fd);
    gemm_tc<1, false><<<gD, 256, GSMEM>>>(ffh, ffl, Fd, w2h, w2l, Fd, Fd, 1, 0, b2, hbuf, sb, nullptr, nullptr, D);
    ln_k<false><<<TOK / 8, 256>>>(sb, g2, be2, out, nullptr, nullptr);
}

// round 4
// speedup vs baseline: 2.6292x; 1.3980x over previous
#include <cuda_runtime.h>
#include <cuda_bf16.h>
#include <cstdint>
#include <math.h>

using bf16 = __nv_bfloat16;

// ---------------- problem constants ----------------
constexpr int Bd  = 4;
constexpr int S1  = 64;
constexpr int S2  = 256;
constexpr int D   = 256;
constexpr int Hh  = 8;
constexpr int HD  = 32;
constexpr int Fd  = 1024;
constexpr int TOK = Bd * S1 * S2;     // 65536
constexpr int BN_ = Bd * S1;          // 256
constexpr int SP  = S2 + 2;           // padded time length 258

// ---------------- scratch (device globals) ----------------
__device__ bf16  g_xph[BN_ * SP * D];
__device__ bf16  g_xpl[BN_ * SP * D];
__device__ bf16  g_qh [TOK * D];
__device__ bf16  g_ql [TOK * D];
__device__ bf16  g_kh [TOK * D];
__device__ bf16  g_kl [TOK * D];
__device__ float g_v  [TOK * D];
__device__ bf16  g_aoh[TOK * D];
__device__ bf16  g_aol[TOK * D];
__device__ float g_s  [TOK * D];
__device__ float g_h  [TOK * D];
__device__ bf16  g_hh [TOK * D];
__device__ bf16  g_hl [TOK * D];
__device__ bf16  g_ffh[TOK * Fd];
__device__ bf16  g_ffl[TOK * Fd];
// transposed weights, hi/lo
__device__ bf16 g_wqh[D * 3 * D], g_wql[D * 3 * D];
__device__ bf16 g_wkh[D * 3 * D], g_wkl[D * 3 * D];
__device__ bf16 g_wvh[D * D],     g_wvl[D * D];
__device__ bf16 g_woh[D * D],     g_wol[D * D];
__device__ bf16 g_w1h[Fd * D],    g_w1l[Fd * D];
__device__ bf16 g_w2h[D * Fd],    g_w2l[D * Fd];

// ---------------- helpers ----------------
__device__ __forceinline__ uint32_t smem_to_u32(const void* p) {
    uint32_t a;
    asm("{ .reg .u64 t; cvta.to.shared.u64 t, %1; cvt.u32.u64 %0, t; }" : "=r"(a) : "l"(p));
    return a;
}
#define CP_ASYNC16(s, g) \
    asm volatile("cp.async.cg.shared.global [%0], [%1], 16;" :: "r"((uint32_t)(s)), "l"(g))
#define CP_ASYNC_COMMIT() asm volatile("cp.async.commit_group;" ::: "memory")
#define SW128(o) ((o) ^ (((o) >> 3) & 0x70))

__device__ __forceinline__ void ldsm4(uint32_t addr, uint32_t& r0, uint32_t& r1,
                                      uint32_t& r2, uint32_t& r3) {
    asm volatile("ldmatrix.sync.aligned.m8n8.x4.shared.b16 {%0,%1,%2,%3}, [%4];"
                 : "=r"(r0), "=r"(r1), "=r"(r2), "=r"(r3) : "r"(addr));
}
__device__ __forceinline__ void mma_bf16(float* c, const uint32_t* a, const uint32_t* b) {
    asm volatile("mma.sync.aligned.m16n8k16.row.col.f32.bf16.bf16.f32 "
                 "{%0,%1,%2,%3}, {%4,%5,%6,%7}, {%8,%9}, {%0,%1,%2,%3};"
                 : "+f"(c[0]), "+f"(c[1]), "+f"(c[2]), "+f"(c[3])
                 : "r"(a[0]), "r"(a[1]), "r"(a[2]), "r"(a[3]), "r"(b[0]), "r"(b[1]));
}
__device__ __forceinline__ void split_bf16(float v, bf16& h, bf16& l) {
    h = __float2bfloat16(v);
    l = __float2bfloat16(v - __bfloat162float(h));
}
__device__ __forceinline__ uint32_t pack2(bf16 a, bf16 b) {
    __nv_bfloat162 p; p.x = a; p.y = b;
    return *(uint32_t*)&p;
}

// ---------------------------------------------------------------------------
// Tensor-core GEMM via mma.sync bf16, 128x128 block tile, BK=64, split-bf16
// (3 accumulating passes), cp.async double buffering.
// EPI: 0 = bias*scl -> fp32 ; 1 = bias*scl + R -> fp32 ;
//      2 = bias*scl + leaky -> bf16 hi/lo ; 3 = bias*scl -> bf16 hi/lo
// ---------------------------------------------------------------------------
template<int EPI, bool CONV>
__global__ __launch_bounds__(256)
void gemm_tc(const bf16* __restrict__ Ah, const bf16* __restrict__ Al, int ldA,
             const bf16* __restrict__ Bh, const bf16* __restrict__ Bl, int ldB,
             int Ktap, int ntaps, int tapbase, float scl,
             const float* __restrict__ bias, const float* __restrict__ R,
             float* __restrict__ Cf, bf16* __restrict__ Ch, bf16* __restrict__ Cl,
             int Nt)
{
    extern __shared__ char smem[];
    const uint32_t sbase = smem_to_u32(smem);
    const int tid = threadIdx.x, wid = tid >> 5, lane = tid & 31;
    const int m0 = blockIdx.y * 128, n0 = blockIdx.x * 128;

    int rowbase;
    if (CONV) { const int bn = m0 >> 8; const int t0 = m0 & 255; rowbase = bn * SP + t0 + tapbase; }
    else      { rowbase = m0; }

    const int kcpt = Ktap >> 6;
    const int nch  = ntaps * kcpt;
    const int c16  = tid & 7;

    auto load_chunk = [&](int c, int stage) {
        const int tap = c / kcpt;
        const int kt  = (c - tap * kcpt) << 6;
        const size_t aoff = (size_t)(rowbase + tap) * ldA + kt + c16 * 8;
        const size_t boff = (size_t)n0 * ldB + (size_t)tap * Ktap + kt + c16 * 8;
        const uint32_t st = sbase + stage * 65536;
#pragma unroll
        for (int i = 0; i < 4; i++) {
            const int row = (tid >> 3) + i * 32;
            const uint32_t so = SW128((uint32_t)(row * 128 + c16 * 16));
            CP_ASYNC16(st +         so, Ah + aoff + (size_t)row * ldA);
            CP_ASYNC16(st + 16384 + so, Al + aoff + (size_t)row * ldA);
            CP_ASYNC16(st + 32768 + so, Bh + boff + (size_t)row * ldB);
            CP_ASYNC16(st + 49152 + so, Bl + boff + (size_t)row * ldB);
        }
        CP_ASYNC_COMMIT();
    };

    load_chunk(0, 0);
    load_chunk(1, 1);

    const int wm  = wid & 1,  wn  = wid >> 1;
    const int m0w = wm * 64,  n0w = wn * 32;
    const int tq  = lane >> 3, rin = lane & 7;
    const int aRow = m0w + (tq & 1) * 8 + rin;
    const int akh  = tq >> 1;
    const int bRow = n0w + (tq >> 1) * 8 + rin;
    const int bkh  = tq & 1;

    float acc[4][4][4];
#pragma unroll
    for (int i = 0; i < 4; i++)
#pragma unroll
        for (int j = 0; j < 4; j++)
#pragma unroll
            for (int r = 0; r < 4; r++) acc[i][j][r] = 0.f;

    for (int c = 0; c < nch; c++) {
        if (c + 1 < nch) asm volatile("cp.async.wait_group 1;" ::: "memory");
        else             asm volatile("cp.async.wait_group 0;" ::: "memory");
        __syncthreads();

        const uint32_t Ab = sbase + (c & 1) * 65536;
        const uint32_t Bb = Ab + 32768;

#pragma unroll
        for (int ks = 0; ks < 4; ks++) {
            uint32_t ah[4][4], al[4][4], bh[4][2], bl[4][2];
#pragma unroll
            for (int mt = 0; mt < 4; mt++) {
                const uint32_t ad = Ab + (uint32_t)((aRow + mt * 16) * 128)
                                  + (uint32_t)(((ks * 2 + akh) ^ rin) << 4);
                ldsm4(ad,          ah[mt][0], ah[mt][1], ah[mt][2], ah[mt][3]);
                ldsm4(ad + 16384,  al[mt][0], al[mt][1], al[mt][2], al[mt][3]);
            }
#pragma unroll
            for (int nt2 = 0; nt2 < 2; nt2++) {
                const uint32_t bd = Bb + (uint32_t)((bRow + nt2 * 16) * 128)
                                  + (uint32_t)(((ks * 2 + bkh) ^ rin) << 4);
                uint32_t r0, r1, r2, r3;
                ldsm4(bd, r0, r1, r2, r3);
                bh[nt2 * 2][0] = r0; bh[nt2 * 2][1] = r1;
                bh[nt2 * 2 + 1][0] = r2; bh[nt2 * 2 + 1][1] = r3;
                ldsm4(bd + 16384, r0, r1, r2, r3);
                bl[nt2 * 2][0] = r0; bl[nt2 * 2][1] = r1;
                bl[nt2 * 2 + 1][0] = r2; bl[nt2 * 2 + 1][1] = r3;
            }
#pragma unroll
            for (int mt = 0; mt < 4; mt++)
#pragma unroll
                for (int nt = 0; nt < 4; nt++) {
                    mma_bf16(acc[mt][nt], ah[mt], bh[nt]);
                    mma_bf16(acc[mt][nt], ah[mt], bl[nt]);
                    mma_bf16(acc[mt][nt], al[mt], bh[nt]);
                }
        }
        __syncthreads();
        if (c + 2 < nch) load_chunk(c + 2, c & 1);
    }

    const int erow = lane >> 2;
    const int ecol = (lane & 3) * 2;
#pragma unroll
    for (int mt = 0; mt < 4; mt++) {
#pragma unroll
        for (int nt = 0; nt < 4; nt++) {
            const int col = n0 + n0w + nt * 8 + ecol;
            const float2 bi = *(const float2*)&bias[col];
#pragma unroll
            for (int half = 0; half < 2; half++) {
                const int row = m0 + m0w + mt * 16 + erow + half * 8;
                float v0 = (acc[mt][nt][half * 2 + 0] + bi.x) * scl;
                float v1 = (acc[mt][nt][half * 2 + 1] + bi.y) * scl;
                if (EPI == 1) {
                    const float2 rr = *(const float2*)&R[(size_t)row * Nt + col];
                    v0 += rr.x; v1 += rr.y;
                }
                if (EPI >= 2) {
                    if (EPI == 2) {
                        v0 = v0 > 0.f ? v0 : 0.01f * v0;
                        v1 = v1 > 0.f ? v1 : 0.01f * v1;
                    }
                    bf16 h0, l0, h1, l1;
                    split_bf16(v0, h0, l0); split_bf16(v1, h1, l1);
                    *(uint32_t*)&Ch[(size_t)row * Nt + col] = pack2(h0, h1);
                    *(uint32_t*)&Cl[(size_t)row * Nt + col] = pack2(l0, l1);
                } else {
                    float2 o; o.x = v0; o.y = v1;
                    *(float2*)&Cf[(size_t)row * Nt + col] = o;
                }
            }
        }
    }
}

// ---------------------------------------------------------------------------
// pad + split x into bf16 hi/lo padded buffer [bn][258][256]
// ---------------------------------------------------------------------------
__global__ __launch_bounds__(256)
void padcvt_x(const float* __restrict__ x, bf16* __restrict__ xh, bf16* __restrict__ xl)
{
    const size_t i = (size_t)blockIdx.x * 256 + threadIdx.x;
    const int d = (int)(i & 255);
    const size_t rest = i >> 8;
    const int t = (int)(rest % SP);
    const size_t bn = rest / SP;
    float v = 0.f;
    if (t >= 1 && t <= S2) v = x[(bn * S2 + (t - 1)) * D + d];
    bf16 h, l; split_bf16(v, h, l);
    xh[i] = h; xl[i] = l;
}

// ---------------------------------------------------------------------------
// fused weight transpose+split: 6 weights in one launch (1024 32x32 tiles)
// ---------------------------------------------------------------------------
__global__ __launch_bounds__(256)
void wtall(const float* __restrict__ Wq, const float* __restrict__ Wk,
           const float* __restrict__ Wv, const float* __restrict__ Wo,
           const float* __restrict__ W1, const float* __restrict__ W2,
           bf16* wqh, bf16* wql, bf16* wkh, bf16* wkl,
           bf16* wvh, bf16* wvl, bf16* woh, bf16* wol,
           bf16* w1h, bf16* w1l, bf16* w2h, bf16* w2l)
{
    __shared__ float ts[32][33];
    const int t = blockIdx.x;
    const float* W; bf16 *Bh, *Bl; int K, N, lt;
    if      (t < 192) { W = Wq; Bh = wqh; Bl = wql; K = 768;  N = 256;  lt = t; }
    else if (t < 384) { W = Wk; Bh = wkh; Bl = wkl; K = 768;  N = 256;  lt = t - 192; }
    else if (t < 448) { W = Wv; Bh = wvh; Bl = wvl; K = 256;  N = 256;  lt = t - 384; }
    else if (t < 512) { W = Wo; Bh = woh; Bl = wol; K = 256;  N = 256;  lt = t - 448; }
    else if (t < 768) { W = W1; Bh = w1h; Bl = w1l; K = 256;  N = 1024; lt = t - 512; }
    else              { W = W2; Bh = w2h; Bl = w2l; K = 1024; N = 256;  lt = t - 768; }
    const int ntn = N / 32;
    const int n0 = (lt % ntn) * 32, k0 = (lt / ntn) * 32;
    const int tx = threadIdx.x, ty = threadIdx.y;   // 32 x 8
#pragma unroll
    for (int j = 0; j < 4; j++)
        ts[ty + j * 8][tx] = W[(size_t)(k0 + ty + j * 8) * N + n0 + tx];
    __syncthreads();
#pragma unroll
    for (int j = 0; j < 4; j++) {
        const float v = ts[tx][ty + j * 8];
        bf16 h, l; split_bf16(v, h, l);
        const size_t o = (size_t)(n0 + ty + j * 8) * K + k0 + tx;
        Bh[o] = h; Bl[o] = l;
    }
}

// ---------------------------------------------------------------------------
// Flash attention on tensor cores. One block per (b,n,h); 8 warps x 32 rows.
// Q/K split-bf16 (scores: 3 passes), online softmax over 4 chunks of 64,
// P,V split-bf16 (PV: 3 passes). Q pre-scaled by 1/sqrt(32) in GEMM epilogue.
// smem: Qh(20480) Ql(20480) Kh(20480) Kl(20480) Vth(16896) Vtl(16896)
//   Q/K rows: stride 80B (5 mod 8 -> conflict-free ldmatrix)
//   Vt rows (d-major): stride 528B (33 mod 8 -> conflict-free)
// ---------------------------------------------------------------------------
constexpr int ATT_SMEM = 4 * 20480 + 2 * 16896;   // 115712

__global__ __launch_bounds__(256)
void attn_tc(const bf16* __restrict__ qh, const bf16* __restrict__ ql,
             const bf16* __restrict__ kh, const bf16* __restrict__ kl,
             const float* __restrict__ v,
             bf16* __restrict__ oh, bf16* __restrict__ ol)
{
    extern __shared__ char smem[];
    const uint32_t sb = smem_to_u32(smem);
    const uint32_t Qh = sb, Ql_ = sb + 20480, Kh = sb + 40960, Kl_ = sb + 61440;
    const uint32_t Vth = sb + 81920, Vtl = sb + 98816;
    bf16* vth_p = (bf16*)(smem + 81920);
    bf16* vtl_p = (bf16*)(smem + 98816);

    const int tid = threadIdx.x, wid = tid >> 5, lane = tid & 31;
    const int h = blockIdx.x & 7, bn = blockIdx.x >> 3;
    const size_t gbase = (size_t)bn * 256 * 256 + h * 32;

    // Q/K hi/lo -> smem (stride 80)
    for (int idx = tid; idx < 1024; idx += 256) {
        const int row = idx >> 2, c = idx & 3;
        const size_t g = gbase + (size_t)row * 256 + c * 8;
        const uint32_t so = row * 80 + c * 16;
        CP_ASYNC16(Qh  + so, qh + g);
        CP_ASYNC16(Ql_ + so, ql + g);
        CP_ASYNC16(Kh  + so, kh + g);
        CP_ASYNC16(Kl_ + so, kl + g);
    }
    CP_ASYNC_COMMIT();
    // V fp32 -> split -> transposed smem [d][s] (stride 264 bf16)
    for (int idx = tid; idx < 2048; idx += 256) {
        const int row = idx >> 3, d4 = (idx & 7) * 4;
        const float4 vv = *(const float4*)&v[gbase + (size_t)row * 256 + d4];
        const float va[4] = { vv.x, vv.y, vv.z, vv.w };
#pragma unroll
        for (int i = 0; i < 4; i++) {
            bf16 hb, lb; split_bf16(va[i], hb, lb);
            vth_p[(d4 + i) * 264 + row] = hb;
            vtl_p[(d4 + i) * 264 + row] = lb;
        }
    }
    asm volatile("cp.async.wait_group 0;" ::: "memory");
    __syncthreads();

    const int tq = lane >> 3, rin = lane & 7;
    const int aR  = (tq & 1) * 8 + rin;   // A-frag row within 16
    const int akh = tq >> 1;              // A-frag k-half
    const int bR  = (tq >> 1) * 8 + rin;  // B-frag n within 16
    const int bkh = tq & 1;               // B-frag k-half

    // preload Q fragments (rows fixed per warp)
    uint32_t qfh[2][2][4], qfl[2][2][4];
#pragma unroll
    for (int mt = 0; mt < 2; mt++)
#pragma unroll
        for (int ks = 0; ks < 2; ks++) {
            const uint32_t ad = Qh + (uint32_t)((wid * 32 + mt * 16 + aR) * 80)
                              + (uint32_t)((ks * 2 + akh) * 16);
            ldsm4(ad,          qfh[mt][ks][0], qfh[mt][ks][1], qfh[mt][ks][2], qfh[mt][ks][3]);
            ldsm4(ad + 20480,  qfl[mt][ks][0], qfl[mt][ks][1], qfl[mt][ks][2], qfl[mt][ks][3]);
        }

    float O[2][4][4];
#pragma unroll
    for (int mt = 0; mt < 2; mt++)
#pragma unroll
        for (int j = 0; j < 4; j++)
#pragma unroll
            for (int r = 0; r < 4; r++) O[mt][j][r] = 0.f;
    float mrow[2][2] = { {-1e30f, -1e30f}, {-1e30f, -1e30f} };
    float lrow[2][2] = { {0.f, 0.f}, {0.f, 0.f} };

    for (int s0 = 0; s0 < 256; s0 += 64) {
        // ---- scores S[32 rows][64 cols] (3-pass split) ----
        float acc[2][8][4];
#pragma unroll
        for (int mt = 0; mt < 2; mt++)
#pragma unroll
            for (int j = 0; j < 8; j++)
#pragma unroll
                for (int r = 0; r < 4; r++) acc[mt][j][r] = 0.f;

#pragma unroll
        for (int ks = 0; ks < 2; ks++) {
            uint32_t kbh[8][2], kbl[8][2];
#pragma unroll
            for (int g = 0; g < 4; g++) {
                const uint32_t kd = Kh + (uint32_t)((s0 + g * 16 + bR) * 80)
                                  + (uint32_t)((ks * 2 + bkh) * 16);
                uint32_t r0, r1, r2, r3;
                ldsm4(kd, r0, r1, r2, r3);
                kbh[g * 2][0] = r0; kbh[g * 2][1] = r1;
                kbh[g * 2 + 1][0] = r2; kbh[g * 2 + 1][1] = r3;
                ldsm4(kd + 20480, r0, r1, r2, r3);
                kbl[g * 2][0] = r0; kbl[g * 2][1] = r1;
                kbl[g * 2 + 1][0] = r2; kbl[g * 2 + 1][1] = r3;
            }
#pragma unroll
            for (int mt = 0; mt < 2; mt++)
#pragma unroll
                for (int j = 0; j < 8; j++) {
                    mma_bf16(acc[mt][j], qfh[mt][ks], kbh[j]);
                    mma_bf16(acc[mt][j], qfh[mt][ks], kbl[j]);
                    mma_bf16(acc[mt][j], qfl[mt][ks], kbh[j]);
                }
        }

        // ---- online softmax ----
#pragma unroll
        for (int mt = 0; mt < 2; mt++) {
            float mxA = -1e30f, mxB = -1e30f;
#pragma unroll
            for (int j = 0; j < 8; j++) {
                mxA = fmaxf(mxA, fmaxf(acc[mt][j][0], acc[mt][j][1]));
                mxB = fmaxf(mxB, fmaxf(acc[mt][j][2], acc[mt][j][3]));
            }
            mxA = fmaxf(mxA, __shfl_xor_sync(0xffffffffu, mxA, 1));
            mxA = fmaxf(mxA, __shfl_xor_sync(0xffffffffu, mxA, 2));
            mxB = fmaxf(mxB, __shfl_xor_sync(0xffffffffu, mxB, 1));
            mxB = fmaxf(mxB, __shfl_xor_sync(0xffffffffu, mxB, 2));
            const float mnA = fmaxf(mrow[mt][0], mxA);
            const float mnB = fmaxf(mrow[mt][1], mxB);
            const float fA = __expf(mrow[mt][0] - mnA);
            const float fB = __expf(mrow[mt][1] - mnB);
            mrow[mt][0] = mnA; mrow[mt][1] = mnB;
            float sA = 0.f, sB = 0.f;
#pragma unroll
            for (int j = 0; j < 8; j++) {
                acc[mt][j][0] = __expf(acc[mt][j][0] - mnA);
                acc[mt][j][1] = __expf(acc[mt][j][1] - mnA);
                acc[mt][j][2] = __expf(acc[mt][j][2] - mnB);
                acc[mt][j][3] = __expf(acc[mt][j][3] - mnB);
                sA += acc[mt][j][0] + acc[mt][j][1];
                sB += acc[mt][j][2] + acc[mt][j][3];
            }
            lrow[mt][0] = lrow[mt][0] * fA + sA;
            lrow[mt][1] = lrow[mt][1] * fB + sB;
#pragma unroll
            for (int j = 0; j < 4; j++) {
                O[mt][j][0] *= fA; O[mt][j][1] *= fA;
                O[mt][j][2] *= fB; O[mt][j][3] *= fB;
            }
        }

        // ---- O += P * V (3-pass split) ----
#pragma unroll
        for (int kt = 0; kt < 4; kt++) {
            uint32_t vbh[4][2], vbl[4][2];
#pragma unroll
            for (int g2 = 0; g2 < 2; g2++) {
                const uint32_t vd = Vth + (uint32_t)((g2 * 16 + bR) * 528)
                                  + (uint32_t)((s0 + kt * 16) * 2 + bkh * 16);
                uint32_t r0, r1, r2, r3;
                ldsm4(vd, r0, r1, r2, r3);
                vbh[g2 * 2][0] = r0; vbh[g2 * 2][1] = r1;
                vbh[g2 * 2 + 1][0] = r2; vbh[g2 * 2 + 1][1] = r3;
                ldsm4(vd + 16896, r0, r1, r2, r3);
                vbl[g2 * 2][0] = r0; vbl[g2 * 2][1] = r1;
                vbl[g2 * 2 + 1][0] = r2; vbl[g2 * 2 + 1][1] = r3;
            }
#pragma unroll
            for (int mt = 0; mt < 2; mt++) {
                uint32_t ph[4], pl[4];
#pragma unroll
                for (int half = 0; half < 2; half++) {     // which n8-tile of the k16
                    const int j = 2 * kt + half;
                    bf16 h0, l0, h1, l1, h2, l2, h3, l3;
                    split_bf16(acc[mt][j][0], h0, l0);
                    split_bf16(acc[mt][j][1], h1, l1);
                    split_bf16(acc[mt][j][2], h2, l2);
                    split_bf16(acc[mt][j][3], h3, l3);
                    ph[half * 2 + 0] = pack2(h0, h1);  pl[half * 2 + 0] = pack2(l0, l1);
                    ph[half * 2 + 1] = pack2(h2, h3);  pl[half * 2 + 1] = pack2(l2, l3);
                }
#pragma unroll
                for (int j2 = 0; j2 < 4; j2++) {
                    mma_bf16(O[mt][j2], ph, vbh[j2]);
                    mma_bf16(O[mt][j2], ph, vbl[j2]);
                    mma_bf16(O[mt][j2], pl, vbh[j2]);
                }
            }
        }
    }

    // ---- epilogue ----
#pragma unroll
    for (int mt = 0; mt < 2; mt++) {
        float lA = lrow[mt][0], lB = lrow[mt][1];
        lA += __shfl_xor_sync(0xffffffffu, lA, 1);
        lA += __shfl_xor_sync(0xffffffffu, lA, 2);
        lB += __shfl_xor_sync(0xffffffffu, lB, 1);
        lB += __shfl_xor_sync(0xffffffffu, lB, 2);
        const float invA = 1.f / lA, invB = 1.f / lB;
        const int rowA = wid * 32 + mt * 16 + (lane >> 2);
        const size_t gA = gbase + (size_t)rowA * 256;
        const size_t gB = gA + (size_t)8 * 256;
#pragma unroll
        for (int j2 = 0; j2 < 4; j2++) {
            const int col = j2 * 8 + (lane & 3) * 2;
            const float a0 = O[mt][j2][0] * invA, a1 = O[mt][j2][1] * invA;
            const float b0 = O[mt][j2][2] * invB, b1 = O[mt][j2][3] * invB;
            bf16 h0, l0, h1, l1;
            split_bf16(a0, h0, l0); split_bf16(a1, h1, l1);
            *(uint32_t*)&oh[gA + col] = pack2(h0, h1);
            *(uint32_t*)&ol[gA + col] = pack2(l0, l1);
            split_bf16(b0, h0, l0); split_bf16(b1, h1, l1);
            *(uint32_t*)&oh[gB + col] = pack2(h0, h1);
            *(uint32_t*)&ol[gB + col] = pack2(l0, l1);
        }
    }
}

// ---------------------------------------------------------------------------
// LayerNorm (D=256). Optionally emits bf16 hi/lo of the normalized output.
// ---------------------------------------------------------------------------
template<bool EMIT>
__global__ __launch_bounds__(256)
void ln_k(const float* __restrict__ X, const float* __restrict__ g,
          const float* __restrict__ be, float* __restrict__ Y,
          bf16* __restrict__ Yh, bf16* __restrict__ Yl)
{
    const int r    = blockIdx.x * 8 + (threadIdx.x >> 5);
    const int lane = threadIdx.x & 31;
    const float* xr = X + (long long)r * D;

    float xv[8];
    float s = 0.f, ss = 0.f;
#pragma unroll
    for (int j = 0; j < 8; j++) {
        const float t = xr[lane + j * 32];
        xv[j] = t; s += t; ss += t * t;
    }
#pragma unroll
    for (int ofs = 16; ofs > 0; ofs >>= 1) {
        s  += __shfl_xor_sync(0xffffffffu, s,  ofs);
        ss += __shfl_xor_sync(0xffffffffu, ss, ofs);
    }
    const float mu  = s * (1.f / 256.f);
    const float var = ss * (1.f / 256.f) - mu * mu;
    const float rs  = rsqrtf(var + 1e-5f);

#pragma unroll
    for (int j = 0; j < 8; j++) {
        const int d = lane + j * 32;
        const float y = (xv[j] - mu) * rs * g[d] + be[d];
        Y[(long long)r * D + d] = y;
        if (EMIT) {
            bf16 h, l; split_bf16(y, h, l);
            Yh[(long long)r * D + d] = h;
            Yl[(long long)r * D + d] = l;
        }
    }
}

// ---------------------------------------------------------------------------
extern "C" void kernel_launch(void* const* d_in, const int* in_sizes, int n_in,
                              void* d_out, int out_size)
{
    const float* x   = (const float*)d_in[0];
    const float* Wq  = (const float*)d_in[1];
    const float* bq  = (const float*)d_in[2];
    const float* Wk  = (const float*)d_in[3];
    const float* bk  = (const float*)d_in[4];
    const float* Wv  = (const float*)d_in[5];
    const float* bv  = (const float*)d_in[6];
    const float* Wo  = (const float*)d_in[7];
    const float* bo  = (const float*)d_in[8];
    const float* W1  = (const float*)d_in[9];
    const float* b1  = (const float*)d_in[10];
    const float* W2  = (const float*)d_in[11];
    const float* b2  = (const float*)d_in[12];
    const float* g1  = (const float*)d_in[13];
    const float* be1 = (const float*)d_in[14];
    const float* g2  = (const float*)d_in[15];
    const float* be2 = (const float*)d_in[16];
    float* out = (float*)d_out;

    bf16 *xph, *xpl, *qh, *ql, *kh, *kl, *aoh, *aol, *hh, *hl, *ffh, *ffl;
    bf16 *wqh, *wql, *wkh, *wkl, *wvh, *wvl, *woh, *wol, *w1h, *w1l, *w2h, *w2l;
    float *v, *sb, *hbuf;
    cudaGetSymbolAddress((void**)&xph, g_xph); cudaGetSymbolAddress((void**)&xpl, g_xpl);
    cudaGetSymbolAddress((void**)&qh,  g_qh);  cudaGetSymbolAddress((void**)&ql,  g_ql);
    cudaGetSymbolAddress((void**)&kh,  g_kh);  cudaGetSymbolAddress((void**)&kl,  g_kl);
    cudaGetSymbolAddress((void**)&v,   g_v);
    cudaGetSymbolAddress((void**)&aoh, g_aoh); cudaGetSymbolAddress((void**)&aol, g_aol);
    cudaGetSymbolAddress((void**)&sb,  g_s);   cudaGetSymbolAddress((void**)&hbuf, g_h);
    cudaGetSymbolAddress((void**)&hh,  g_hh);  cudaGetSymbolAddress((void**)&hl,  g_hl);
    cudaGetSymbolAddress((void**)&ffh, g_ffh); cudaGetSymbolAddress((void**)&ffl, g_ffl);
    cudaGetSymbolAddress((void**)&wqh, g_wqh); cudaGetSymbolAddress((void**)&wql, g_wql);
    cudaGetSymbolAddress((void**)&wkh, g_wkh); cudaGetSymbolAddress((void**)&wkl, g_wkl);
    cudaGetSymbolAddress((void**)&wvh, g_wvh); cudaGetSymbolAddress((void**)&wvl, g_wvl);
    cudaGetSymbolAddress((void**)&woh, g_woh); cudaGetSymbolAddress((void**)&wol, g_wol);
    cudaGetSymbolAddress((void**)&w1h, g_w1h); cudaGetSymbolAddress((void**)&w1l, g_w1l);
    cudaGetSymbolAddress((void**)&w2h, g_w2h); cudaGetSymbolAddress((void**)&w2l, g_w2l);

    constexpr int GSMEM = 2 * 65536;
    cudaFuncSetAttribute(gemm_tc<0, true>,  cudaFuncAttributeMaxDynamicSharedMemorySize, GSMEM);
    cudaFuncSetAttribute(gemm_tc<3, true>,  cudaFuncAttributeMaxDynamicSharedMemorySize, GSMEM);
    cudaFuncSetAttribute(gemm_tc<1, false>, cudaFuncAttributeMaxDynamicSharedMemorySize, GSMEM);
    cudaFuncSetAttribute(gemm_tc<2, false>, cudaFuncAttributeMaxDynamicSharedMemorySize, GSMEM);
    cudaFuncSetAttribute(attn_tc, cudaFuncAttributeMaxDynamicSharedMemorySize, ATT_SMEM);

    // 0: pad/split x ; 1: all weight converts
    padcvt_x<<<(BN_ * SP * D) / 256, 256>>>(x, xph, xpl);
    wtall<<<1024, dim3(32, 8)>>>(Wq, Wk, Wv, Wo, W1, W2,
                                 wqh, wql, wkh, wkl, wvh, wvl,
                                 woh, wol, w1h, w1l, w2h, w2l);

    const dim3 gD(D / 128,  TOK / 128);
    const dim3 gF(Fd / 128, TOK / 128);
    const float qscale = 0.17677669529663687f;   // 1/sqrt(32)

    // 2,3: Q,K (3-tap conv; bf16 hi/lo out; Q pre-scaled) ; 4: V (fp32 out)
    gemm_tc<3, true><<<gD, 256, GSMEM>>>(xph, xpl, D, wqh, wql, 3 * D, D, 3, 0, qscale,
                                         bq, nullptr, nullptr, qh, ql, D);
    gemm_tc<3, true><<<gD, 256, GSMEM>>>(xph, xpl, D, wkh, wkl, 3 * D, D, 3, 0, 1.f,
                                         bk, nullptr, nullptr, kh, kl, D);
    gemm_tc<0, true><<<gD, 256, GSMEM>>>(xph, xpl, D, wvh, wvl, D,     D, 1, 1, 1.f,
                                         bv, nullptr, v, nullptr, nullptr, D);
    // 5: flash attention (tensor cores)
    attn_tc<<<Bd * S1 * Hh, 256, ATT_SMEM>>>(qh, ql, kh, kl, v, aoh, aol);
    // 6: s = x + ao@Wo + bo ; 7: h = LN1(s) (emits hi/lo)
    gemm_tc<1, false><<<gD, 256, GSMEM>>>(aoh, aol, D, woh, wol, D, D, 1, 0, 1.f,
                                          bo, x, sb, nullptr, nullptr, D);
    ln_k<true><<<TOK / 8, 256>>>(sb, g1, be1, hbuf, hh, hl);
    // 8: ff = leaky(h@W1+b1) ; 9: s = h + ff@W2 + b2 ; 10: out = LN2(s)
    gemm_tc<2, false><<<gF, 256, GSMEM>>>(hh, hl, D, w1h, w1l, D, D, 1, 0, 1.f,
                                          b1, nullptr, nullptr, ffh, ffl, Fd);
    gemm_tc<1, false><<<gD, 256, GSMEM>>>(ffh, ffl, Fd, w2h, w2l, Fd, Fd, 1, 0, 1.f,
                                          b2, hbuf, sb, nullptr, nullptr, D);
    ln_k<false><<<TOK / 8, 256>>>(sb, g2, be2, out, nullptr, nullptr);
}

// round 5
// speedup vs baseline: 2.7992x; 1.0646x over previous
#include <cuda_runtime.h>
#include <cuda_bf16.h>
#include <cstdint>
#include <math.h>

using bf16 = __nv_bfloat16;

// ---------------- problem constants ----------------
constexpr int Bd  = 4;
constexpr int S1  = 64;
constexpr int S2  = 256;
constexpr int D   = 256;
constexpr int Hh  = 8;
constexpr int HD  = 32;
constexpr int Fd  = 1024;
constexpr int TOK = Bd * S1 * S2;     // 65536
constexpr int BN_ = Bd * S1;          // 256
constexpr int SP  = S2 + 2;           // padded time length 258

// ---------------- scratch (device globals) ----------------
__device__ bf16  g_xph[BN_ * SP * D];
__device__ bf16  g_xpl[BN_ * SP * D];
__device__ bf16  g_qh [TOK * D];
__device__ bf16  g_ql [TOK * D];
__device__ bf16  g_kh [TOK * D];
__device__ bf16  g_kl [TOK * D];
__device__ float g_v  [TOK * D];
__device__ bf16  g_aoh[TOK * D];
__device__ bf16  g_aol[TOK * D];
__device__ float g_s  [TOK * D];
__device__ float g_h  [TOK * D];
__device__ bf16  g_hh [TOK * D];
__device__ bf16  g_hl [TOK * D];
__device__ bf16  g_ffh[TOK * Fd];
__device__ bf16  g_ffl[TOK * Fd];
// transposed weights, hi/lo
__device__ bf16 g_wqh[D * 3 * D], g_wql[D * 3 * D];
__device__ bf16 g_wkh[D * 3 * D], g_wkl[D * 3 * D];
__device__ bf16 g_wvh[D * D],     g_wvl[D * D];
__device__ bf16 g_woh[D * D],     g_wol[D * D];
__device__ bf16 g_w1h[Fd * D],    g_w1l[Fd * D];
__device__ bf16 g_w2h[D * Fd],    g_w2l[D * Fd];

// ---------------- helpers ----------------
__device__ __forceinline__ uint32_t smem_to_u32(const void* p) {
    uint32_t a;
    asm("{ .reg .u64 t; cvta.to.shared.u64 t, %1; cvt.u32.u64 %0, t; }" : "=r"(a) : "l"(p));
    return a;
}
#define CP_ASYNC16(s, g) \
    asm volatile("cp.async.cg.shared.global [%0], [%1], 16;" :: "r"((uint32_t)(s)), "l"(g))
#define CP_ASYNC_COMMIT() asm volatile("cp.async.commit_group;" ::: "memory")

__device__ __forceinline__ void ldsm4(uint32_t addr, uint32_t& r0, uint32_t& r1,
                                      uint32_t& r2, uint32_t& r3) {
    asm volatile("ldmatrix.sync.aligned.m8n8.x4.shared.b16 {%0,%1,%2,%3}, [%4];"
                 : "=r"(r0), "=r"(r1), "=r"(r2), "=r"(r3) : "r"(addr));
}
__device__ __forceinline__ void mma_bf16(float* c, const uint32_t* a, const uint32_t* b) {
    asm volatile("mma.sync.aligned.m16n8k16.row.col.f32.bf16.bf16.f32 "
                 "{%0,%1,%2,%3}, {%4,%5,%6,%7}, {%8,%9}, {%0,%1,%2,%3};"
                 : "+f"(c[0]), "+f"(c[1]), "+f"(c[2]), "+f"(c[3])
                 : "r"(a[0]), "r"(a[1]), "r"(a[2]), "r"(a[3]), "r"(b[0]), "r"(b[1]));
}
__device__ __forceinline__ void split_bf16(float v, bf16& h, bf16& l) {
    h = __float2bfloat16(v);
    l = __float2bfloat16(v - __bfloat162float(h));
}
__device__ __forceinline__ uint32_t pack2(bf16 a, bf16 b) {
    __nv_bfloat162 p; p.x = a; p.y = b;
    return *(uint32_t*)&p;
}
// 64B-row swizzle: 4 16B columns, rotate by (row>>1)&3 -> conflict-free ldsm + stores
__device__ __forceinline__ uint32_t sw64(int row, int c) {
    return (uint32_t)(row * 64 + ((c ^ ((row >> 1) & 3)) << 4));
}

// ---------------------------------------------------------------------------
// Tensor-core GEMM via mma.sync bf16, 128x128 block tile, BK=32, split-bf16
// (3 accumulating passes), cp.async 3-stage pipeline, 2 CTAs/SM.
// smem stage (32KB): [Ah 8K][Al 8K][Bh 8K][Bl 8K]
// EPI: 0 = bias*scl -> fp32 ; 1 = bias*scl + R -> fp32 ;
//      2 = bias*scl + leaky -> bf16 hi/lo ; 3 = bias*scl -> bf16 hi/lo
// ---------------------------------------------------------------------------
constexpr int GSTAGE = 32768;
constexpr int GSMEM  = 3 * GSTAGE;   // 98304

template<int EPI, bool CONV>
__global__ __launch_bounds__(256, 2)
void gemm_tc(const bf16* __restrict__ Ah, const bf16* __restrict__ Al, int ldA,
             const bf16* __restrict__ Bh, const bf16* __restrict__ Bl, int ldB,
             int Ktap, int ntaps, int tapbase, float scl,
             const float* __restrict__ bias, const float* __restrict__ R,
             float* __restrict__ Cf, bf16* __restrict__ Ch, bf16* __restrict__ Cl,
             int Nt)
{
    extern __shared__ char smem[];
    const uint32_t sbase = smem_to_u32(smem);
    const int tid = threadIdx.x, wid = tid >> 5, lane = tid & 31;
    const int m0 = blockIdx.y * 128, n0 = blockIdx.x * 128;

    int rowbase;
    if (CONV) { const int bn = m0 >> 8; const int t0 = m0 & 255; rowbase = bn * SP + t0 + tapbase; }
    else      { rowbase = m0; }

    const int kcpt = Ktap >> 5;          // 32-wide K chunks per tap
    const int nch  = ntaps * kcpt;
    const int c4   = tid & 3;            // 16B column 0..3
    const int rw0  = tid >> 2;           // row 0..63

    auto load_chunk = [&](int c, int stage) {
        const int tap = c / kcpt;
        const int kt  = (c - tap * kcpt) << 5;
        const size_t aoff = (size_t)(rowbase + tap) * ldA + kt + c4 * 8;
        const size_t boff = (size_t)n0 * ldB + (size_t)tap * Ktap + kt + c4 * 8;
        const uint32_t st = sbase + stage * GSTAGE;
#pragma unroll
        for (int i = 0; i < 2; i++) {
            const int row = rw0 + i * 64;
            const uint32_t so = sw64(row, c4);
            CP_ASYNC16(st +         so, Ah + aoff + (size_t)row * ldA);
            CP_ASYNC16(st +  8192 + so, Al + aoff + (size_t)row * ldA);
            CP_ASYNC16(st + 16384 + so, Bh + boff + (size_t)row * ldB);
            CP_ASYNC16(st + 24576 + so, Bl + boff + (size_t)row * ldB);
        }
        CP_ASYNC_COMMIT();
    };

    load_chunk(0, 0);
    load_chunk(1, 1);
    load_chunk(2, 2);

    const int wm  = wid & 1,  wn  = wid >> 1;
    const int m0w = wm * 64,  n0w = wn * 32;
    const int tq  = lane >> 3, rin = lane & 7;
    const int aRow = m0w + (tq & 1) * 8 + rin;
    const int akh  = tq >> 1;
    const int bRow = n0w + (tq >> 1) * 8 + rin;
    const int bkh  = tq & 1;

    float acc[4][4][4];
#pragma unroll
    for (int i = 0; i < 4; i++)
#pragma unroll
        for (int j = 0; j < 4; j++)
#pragma unroll
            for (int r = 0; r < 4; r++) acc[i][j][r] = 0.f;

    for (int c = 0; c < nch; c++) {
        const int pend = nch - 1 - c;
        if      (pend >= 2) asm volatile("cp.async.wait_group 2;" ::: "memory");
        else if (pend == 1) asm volatile("cp.async.wait_group 1;" ::: "memory");
        else                asm volatile("cp.async.wait_group 0;" ::: "memory");
        __syncthreads();

        const uint32_t Ab = sbase + (c % 3) * GSTAGE;
        const uint32_t Bb = Ab + 16384;

#pragma unroll
        for (int ks = 0; ks < 2; ks++) {
            uint32_t ah[4][4], al[4][4], bh[4][2], bl[4][2];
#pragma unroll
            for (int mt = 0; mt < 4; mt++) {
                const int r = aRow + mt * 16;
                const uint32_t ad = Ab + sw64(r, ks * 2 + akh);
                ldsm4(ad,         ah[mt][0], ah[mt][1], ah[mt][2], ah[mt][3]);
                ldsm4(ad + 8192,  al[mt][0], al[mt][1], al[mt][2], al[mt][3]);
            }
#pragma unroll
            for (int nt2 = 0; nt2 < 2; nt2++) {
                const int r = bRow + nt2 * 16;
                const uint32_t bd = Bb + sw64(r, ks * 2 + bkh);
                uint32_t r0, r1, r2, r3;
                ldsm4(bd, r0, r1, r2, r3);
                bh[nt2 * 2][0] = r0; bh[nt2 * 2][1] = r1;
                bh[nt2 * 2 + 1][0] = r2; bh[nt2 * 2 + 1][1] = r3;
                ldsm4(bd + 8192, r0, r1, r2, r3);
                bl[nt2 * 2][0] = r0; bl[nt2 * 2][1] = r1;
                bl[nt2 * 2 + 1][0] = r2; bl[nt2 * 2 + 1][1] = r3;
            }
#pragma unroll
            for (int mt = 0; mt < 4; mt++)
#pragma unroll
                for (int nt = 0; nt < 4; nt++) {
                    mma_bf16(acc[mt][nt], ah[mt], bh[nt]);
                    mma_bf16(acc[mt][nt], ah[mt], bl[nt]);
                    mma_bf16(acc[mt][nt], al[mt], bh[nt]);
                }
        }
        __syncthreads();
        if (c + 3 < nch) load_chunk(c + 3, (c + 3) % 3);
    }

    const int erow = lane >> 2;
    const int ecol = (lane & 3) * 2;
#pragma unroll
    for (int mt = 0; mt < 4; mt++) {
#pragma unroll
        for (int nt = 0; nt < 4; nt++) {
            const int col = n0 + n0w + nt * 8 + ecol;
            const float2 bi = *(const float2*)&bias[col];
#pragma unroll
            for (int half = 0; half < 2; half++) {
                const int row = m0 + m0w + mt * 16 + erow + half * 8;
                float v0 = (acc[mt][nt][half * 2 + 0] + bi.x) * scl;
                float v1 = (acc[mt][nt][half * 2 + 1] + bi.y) * scl;
                if (EPI == 1) {
                    const float2 rr = *(const float2*)&R[(size_t)row * Nt + col];
                    v0 += rr.x; v1 += rr.y;
                }
                if (EPI >= 2) {
                    if (EPI == 2) {
                        v0 = v0 > 0.f ? v0 : 0.01f * v0;
                        v1 = v1 > 0.f ? v1 : 0.01f * v1;
                    }
                    bf16 h0, l0, h1, l1;
                    split_bf16(v0, h0, l0); split_bf16(v1, h1, l1);
                    *(uint32_t*)&Ch[(size_t)row * Nt + col] = pack2(h0, h1);
                    *(uint32_t*)&Cl[(size_t)row * Nt + col] = pack2(l0, l1);
                } else {
                    float2 o; o.x = v0; o.y = v1;
                    *(float2*)&Cf[(size_t)row * Nt + col] = o;
                }
            }
        }
    }
}

// ---------------------------------------------------------------------------
// pad + split x into bf16 hi/lo padded buffer [bn][258][256]
// ---------------------------------------------------------------------------
__global__ __launch_bounds__(256)
void padcvt_x(const float* __restrict__ x, bf16* __restrict__ xh, bf16* __restrict__ xl)
{
    const size_t i = (size_t)blockIdx.x * 256 + threadIdx.x;
    const int d = (int)(i & 255);
    const size_t rest = i >> 8;
    const int t = (int)(rest % SP);
    const size_t bn = rest / SP;
    float v = 0.f;
    if (t >= 1 && t <= S2) v = x[(bn * S2 + (t - 1)) * D + d];
    bf16 h, l; split_bf16(v, h, l);
    xh[i] = h; xl[i] = l;
}

// ---------------------------------------------------------------------------
// fused weight transpose+split: 6 weights in one launch (1024 32x32 tiles)
// ---------------------------------------------------------------------------
__global__ __launch_bounds__(256)
void wtall(const float* __restrict__ Wq, const float* __restrict__ Wk,
           const float* __restrict__ Wv, const float* __restrict__ Wo,
           const float* __restrict__ W1, const float* __restrict__ W2,
           bf16* wqh, bf16* wql, bf16* wkh, bf16* wkl,
           bf16* wvh, bf16* wvl, bf16* woh, bf16* wol,
           bf16* w1h, bf16* w1l, bf16* w2h, bf16* w2l)
{
    __shared__ float ts[32][33];
    const int t = blockIdx.x;
    const float* W; bf16 *Bh, *Bl; int K, N, lt;
    if      (t < 192) { W = Wq; Bh = wqh; Bl = wql; K = 768;  N = 256;  lt = t; }
    else if (t < 384) { W = Wk; Bh = wkh; Bl = wkl; K = 768;  N = 256;  lt = t - 192; }
    else if (t < 448) { W = Wv; Bh = wvh; Bl = wvl; K = 256;  N = 256;  lt = t - 384; }
    else if (t < 512) { W = Wo; Bh = woh; Bl = wol; K = 256;  N = 256;  lt = t - 448; }
    else if (t < 768) { W = W1; Bh = w1h; Bl = w1l; K = 256;  N = 1024; lt = t - 512; }
    else              { W = W2; Bh = w2h; Bl = w2l; K = 1024; N = 256;  lt = t - 768; }
    const int ntn = N / 32;
    const int n0 = (lt % ntn) * 32, k0 = (lt / ntn) * 32;
    const int tx = threadIdx.x, ty = threadIdx.y;   // 32 x 8
#pragma unroll
    for (int j = 0; j < 4; j++)
        ts[ty + j * 8][tx] = W[(size_t)(k0 + ty + j * 8) * N + n0 + tx];
    __syncthreads();
#pragma unroll
    for (int j = 0; j < 4; j++) {
        const float v = ts[tx][ty + j * 8];
        bf16 h, l; split_bf16(v, h, l);
        const size_t o = (size_t)(n0 + ty + j * 8) * K + k0 + tx;
        Bh[o] = h; Bl[o] = l;
    }
}

// ---------------------------------------------------------------------------
// Flash attention on tensor cores. One block per (b,n,h); 8 warps x 32 rows.
// ---------------------------------------------------------------------------
constexpr int ATT_SMEM = 4 * 20480 + 2 * 16896;   // 115712

__global__ __launch_bounds__(256)
void attn_tc(const bf16* __restrict__ qh, const bf16* __restrict__ ql,
             const bf16* __restrict__ kh, const bf16* __restrict__ kl,
             const float* __restrict__ v,
             bf16* __restrict__ oh, bf16* __restrict__ ol)
{
    extern __shared__ char smem[];
    const uint32_t sb = smem_to_u32(smem);
    const uint32_t Qh = sb, Ql_ = sb + 20480, Kh = sb + 40960, Kl_ = sb + 61440;
    const uint32_t Vth = sb + 81920;
    bf16* vth_p = (bf16*)(smem + 81920);
    bf16* vtl_p = (bf16*)(smem + 98816);

    const int tid = threadIdx.x, wid = tid >> 5, lane = tid & 31;
    const int h = blockIdx.x & 7, bn = blockIdx.x >> 3;
    const size_t gbase = (size_t)bn * 256 * 256 + h * 32;

    for (int idx = tid; idx < 1024; idx += 256) {
        const int row = idx >> 2, c = idx & 3;
        const size_t g = gbase + (size_t)row * 256 + c * 8;
        const uint32_t so = row * 80 + c * 16;
        CP_ASYNC16(Qh  + so, qh + g);
        CP_ASYNC16(Ql_ + so, ql + g);
        CP_ASYNC16(Kh  + so, kh + g);
        CP_ASYNC16(Kl_ + so, kl + g);
    }
    CP_ASYNC_COMMIT();
    for (int idx = tid; idx < 2048; idx += 256) {
        const int row = idx >> 3, d4 = (idx & 7) * 4;
        const float4 vv = *(const float4*)&v[gbase + (size_t)row * 256 + d4];
        const float va[4] = { vv.x, vv.y, vv.z, vv.w };
#pragma unroll
        for (int i = 0; i < 4; i++) {
            bf16 hb, lb; split_bf16(va[i], hb, lb);
            vth_p[(d4 + i) * 264 + row] = hb;
            vtl_p[(d4 + i) * 264 + row] = lb;
        }
    }
    asm volatile("cp.async.wait_group 0;" ::: "memory");
    __syncthreads();

    const int tq = lane >> 3, rin = lane & 7;
    const int aR  = (tq & 1) * 8 + rin;
    const int akh = tq >> 1;
    const int bR  = (tq >> 1) * 8 + rin;
    const int bkh = tq & 1;

    uint32_t qfh[2][2][4], qfl[2][2][4];
#pragma unroll
    for (int mt = 0; mt < 2; mt++)
#pragma unroll
        for (int ks = 0; ks < 2; ks++) {
            const uint32_t ad = Qh + (uint32_t)((wid * 32 + mt * 16 + aR) * 80)
                              + (uint32_t)((ks * 2 + akh) * 16);
            ldsm4(ad,          qfh[mt][ks][0], qfh[mt][ks][1], qfh[mt][ks][2], qfh[mt][ks][3]);
            ldsm4(ad + 20480,  qfl[mt][ks][0], qfl[mt][ks][1], qfl[mt][ks][2], qfl[mt][ks][3]);
        }

    float O[2][4][4];
#pragma unroll
    for (int mt = 0; mt < 2; mt++)
#pragma unroll
        for (int j = 0; j < 4; j++)
#pragma unroll
            for (int r = 0; r < 4; r++) O[mt][j][r] = 0.f;
    float mrow[2][2] = { {-1e30f, -1e30f}, {-1e30f, -1e30f} };
    float lrow[2][2] = { {0.f, 0.f}, {0.f, 0.f} };

    for (int s0 = 0; s0 < 256; s0 += 64) {
        float acc[2][8][4];
#pragma unroll
        for (int mt = 0; mt < 2; mt++)
#pragma unroll
            for (int j = 0; j < 8; j++)
#pragma unroll
                for (int r = 0; r < 4; r++) acc[mt][j][r] = 0.f;

#pragma unroll
        for (int ks = 0; ks < 2; ks++) {
            uint32_t kbh[8][2], kbl[8][2];
#pragma unroll
            for (int g = 0; g < 4; g++) {
                const uint32_t kd = Kh + (uint32_t)((s0 + g * 16 + bR) * 80)
                                  + (uint32_t)((ks * 2 + bkh) * 16);
                uint32_t r0, r1, r2, r3;
                ldsm4(kd, r0, r1, r2, r3);
                kbh[g * 2][0] = r0; kbh[g * 2][1] = r1;
                kbh[g * 2 + 1][0] = r2; kbh[g * 2 + 1][1] = r3;
                ldsm4(kd + 20480, r0, r1, r2, r3);
                kbl[g * 2][0] = r0; kbl[g * 2][1] = r1;
                kbl[g * 2 + 1][0] = r2; kbl[g * 2 + 1][1] = r3;
            }
#pragma unroll
            for (int mt = 0; mt < 2; mt++)
#pragma unroll
                for (int j = 0; j < 8; j++) {
                    mma_bf16(acc[mt][j], qfh[mt][ks], kbh[j]);
                    mma_bf16(acc[mt][j], qfh[mt][ks], kbl[j]);
                    mma_bf16(acc[mt][j], qfl[mt][ks], kbh[j]);
                }
        }

#pragma unroll
        for (int mt = 0; mt < 2; mt++) {
            float mxA = -1e30f, mxB = -1e30f;
#pragma unroll
            for (int j = 0; j < 8; j++) {
                mxA = fmaxf(mxA, fmaxf(acc[mt][j][0], acc[mt][j][1]));
                mxB = fmaxf(mxB, fmaxf(acc[mt][j][2], acc[mt][j][3]));
            }
            mxA = fmaxf(mxA, __shfl_xor_sync(0xffffffffu, mxA, 1));
            mxA = fmaxf(mxA, __shfl_xor_sync(0xffffffffu, mxA, 2));
            mxB = fmaxf(mxB, __shfl_xor_sync(0xffffffffu, mxB, 1));
            mxB = fmaxf(mxB, __shfl_xor_sync(0xffffffffu, mxB, 2));
            const float mnA = fmaxf(mrow[mt][0], mxA);
            const float mnB = fmaxf(mrow[mt][1], mxB);
            const float fA = __expf(mrow[mt][0] - mnA);
            const float fB = __expf(mrow[mt][1] - mnB);
            mrow[mt][0] = mnA; mrow[mt][1] = mnB;
            float sA = 0.f, sB = 0.f;
#pragma unroll
            for (int j = 0; j < 8; j++) {
                acc[mt][j][0] = __expf(acc[mt][j][0] - mnA);
                acc[mt][j][1] = __expf(acc[mt][j][1] - mnA);
                acc[mt][j][2] = __expf(acc[mt][j][2] - mnB);
                acc[mt][j][3] = __expf(acc[mt][j][3] - mnB);
                sA += acc[mt][j][0] + acc[mt][j][1];
                sB += acc[mt][j][2] + acc[mt][j][3];
            }
            lrow[mt][0] = lrow[mt][0] * fA + sA;
            lrow[mt][1] = lrow[mt][1] * fB + sB;
#pragma unroll
            for (int j = 0; j < 4; j++) {
                O[mt][j][0] *= fA; O[mt][j][1] *= fA;
                O[mt][j][2] *= fB; O[mt][j][3] *= fB;
            }
        }

#pragma unroll
        for (int kt = 0; kt < 4; kt++) {
            uint32_t vbh[4][2], vbl[4][2];
#pragma unroll
            for (int g2 = 0; g2 < 2; g2++) {
                const uint32_t vd = Vth + (uint32_t)((g2 * 16 + bR) * 528)
                                  + (uint32_t)((s0 + kt * 16) * 2 + bkh * 16);
                uint32_t r0, r1, r2, r3;
                ldsm4(vd, r0, r1, r2, r3);
                vbh[g2 * 2][0] = r0; vbh[g2 * 2][1] = r1;
                vbh[g2 * 2 + 1][0] = r2; vbh[g2 * 2 + 1][1] = r3;
                ldsm4(vd + 16896, r0, r1, r2, r3);
                vbl[g2 * 2][0] = r0; vbl[g2 * 2][1] = r1;
                vbl[g2 * 2 + 1][0] = r2; vbl[g2 * 2 + 1][1] = r3;
            }
#pragma unroll
            for (int mt = 0; mt < 2; mt++) {
                uint32_t ph[4], pl[4];
#pragma unroll
                for (int half = 0; half < 2; half++) {
                    const int j = 2 * kt + half;
                    bf16 h0, l0, h1, l1, h2, l2, h3, l3;
                    split_bf16(acc[mt][j][0], h0, l0);
                    split_bf16(acc[mt][j][1], h1, l1);
                    split_bf16(acc[mt][j][2], h2, l2);
                    split_bf16(acc[mt][j][3], h3, l3);
                    ph[half * 2 + 0] = pack2(h0, h1);  pl[half * 2 + 0] = pack2(l0, l1);
                    ph[half * 2 + 1] = pack2(h2, h3);  pl[half * 2 + 1] = pack2(l2, l3);
                }
#pragma unroll
                for (int j2 = 0; j2 < 4; j2++) {
                    mma_bf16(O[mt][j2], ph, vbh[j2]);
                    mma_bf16(O[mt][j2], ph, vbl[j2]);
                    mma_bf16(O[mt][j2], pl, vbh[j2]);
                }
            }
        }
    }

#pragma unroll
    for (int mt = 0; mt < 2; mt++) {
        float lA = lrow[mt][0], lB = lrow[mt][1];
        lA += __shfl_xor_sync(0xffffffffu, lA, 1);
        lA += __shfl_xor_sync(0xffffffffu, lA, 2);
        lB += __shfl_xor_sync(0xffffffffu, lB, 1);
        lB += __shfl_xor_sync(0xffffffffu, lB, 2);
        const float invA = 1.f / lA, invB = 1.f / lB;
        const int rowA = wid * 32 + mt * 16 + (lane >> 2);
        const size_t gA = gbase + (size_t)rowA * 256;
        const size_t gB = gA + (size_t)8 * 256;
#pragma unroll
        for (int j2 = 0; j2 < 4; j2++) {
            const int col = j2 * 8 + (lane & 3) * 2;
            const float a0 = O[mt][j2][0] * invA, a1 = O[mt][j2][1] * invA;
            const float b0 = O[mt][j2][2] * invB, b1 = O[mt][j2][3] * invB;
            bf16 h0, l0, h1, l1;
            split_bf16(a0, h0, l0); split_bf16(a1, h1, l1);
            *(uint32_t*)&oh[gA + col] = pack2(h0, h1);
            *(uint32_t*)&ol[gA + col] = pack2(l0, l1);
            split_bf16(b0, h0, l0); split_bf16(b1, h1, l1);
            *(uint32_t*)&oh[gB + col] = pack2(h0, h1);
            *(uint32_t*)&ol[gB + col] = pack2(l0, l1);
        }
    }
}

// ---------------------------------------------------------------------------
// LayerNorm (D=256). Optionally emits bf16 hi/lo of the normalized output.
// ---------------------------------------------------------------------------
template<bool EMIT>
__global__ __launch_bounds__(256)
void ln_k(const float* __restrict__ X, const float* __restrict__ g,
          const float* __restrict__ be, float* __restrict__ Y,
          bf16* __restrict__ Yh, bf16* __restrict__ Yl)
{
    const int r    = blockIdx.x * 8 + (threadIdx.x >> 5);
    const int lane = threadIdx.x & 31;
    const float* xr = X + (long long)r * D;

    float xv[8];
    float s = 0.f, ss = 0.f;
#pragma unroll
    for (int j = 0; j < 8; j++) {
        const float t = xr[lane + j * 32];
        xv[j] = t; s += t; ss += t * t;
    }
#pragma unroll
    for (int ofs = 16; ofs > 0; ofs >>= 1) {
        s  += __shfl_xor_sync(0xffffffffu, s,  ofs);
        ss += __shfl_xor_sync(0xffffffffu, ss, ofs);
    }
    const float mu  = s * (1.f / 256.f);
    const float var = ss * (1.f / 256.f) - mu * mu;
    const float rs  = rsqrtf(var + 1e-5f);

#pragma unroll
    for (int j = 0; j < 8; j++) {
        const int d = lane + j * 32;
        const float y = (xv[j] - mu) * rs * g[d] + be[d];
        Y[(long long)r * D + d] = y;
        if (EMIT) {
            bf16 h, l; split_bf16(y, h, l);
            Yh[(long long)r * D + d] = h;
            Yl[(long long)r * D + d] = l;
        }
    }
}

// ---------------------------------------------------------------------------
extern "C" void kernel_launch(void* const* d_in, const int* in_sizes, int n_in,
                              void* d_out, int out_size)
{
    const float* x   = (const float*)d_in[0];
    const float* Wq  = (const float*)d_in[1];
    const float* bq  = (const float*)d_in[2];
    const float* Wk  = (const float*)d_in[3];
    const float* bk  = (const float*)d_in[4];
    const float* Wv  = (const float*)d_in[5];
    const float* bv  = (const float*)d_in[6];
    const float* Wo  = (const float*)d_in[7];
    const float* bo  = (const float*)d_in[8];
    const float* W1  = (const float*)d_in[9];
    const float* b1  = (const float*)d_in[10];
    const float* W2  = (const float*)d_in[11];
    const float* b2  = (const float*)d_in[12];
    const float* g1  = (const float*)d_in[13];
    const float* be1 = (const float*)d_in[14];
    const float* g2  = (const float*)d_in[15];
    const float* be2 = (const float*)d_in[16];
    float* out = (float*)d_out;

    bf16 *xph, *xpl, *qh, *ql, *kh, *kl, *aoh, *aol, *hh, *hl, *ffh, *ffl;
    bf16 *wqh, *wql, *wkh, *wkl, *wvh, *wvl, *woh, *wol, *w1h, *w1l, *w2h, *w2l;
    float *v, *sb, *hbuf;
    cudaGetSymbolAddress((void**)&xph, g_xph); cudaGetSymbolAddress((void**)&xpl, g_xpl);
    cudaGetSymbolAddress((void**)&qh,  g_qh);  cudaGetSymbolAddress((void**)&ql,  g_ql);
    cudaGetSymbolAddress((void**)&kh,  g_kh);  cudaGetSymbolAddress((void**)&kl,  g_kl);
    cudaGetSymbolAddress((void**)&v,   g_v);
    cudaGetSymbolAddress((void**)&aoh, g_aoh); cudaGetSymbolAddress((void**)&aol, g_aol);
    cudaGetSymbolAddress((void**)&sb,  g_s);   cudaGetSymbolAddress((void**)&hbuf, g_h);
    cudaGetSymbolAddress((void**)&hh,  g_hh);  cudaGetSymbolAddress((void**)&hl,  g_hl);
    cudaGetSymbolAddress((void**)&ffh, g_ffh); cudaGetSymbolAddress((void**)&ffl, g_ffl);
    cudaGetSymbolAddress((void**)&wqh, g_wqh); cudaGetSymbolAddress((void**)&wql, g_wql);
    cudaGetSymbolAddress((void**)&wkh, g_wkh); cudaGetSymbolAddress((void**)&wkl, g_wkl);
    cudaGetSymbolAddress((void**)&wvh, g_wvh); cudaGetSymbolAddress((void**)&wvl, g_wvl);
    cudaGetSymbolAddress((void**)&woh, g_woh); cudaGetSymbolAddress((void**)&wol, g_wol);
    cudaGetSymbolAddress((void**)&w1h, g_w1h); cudaGetSymbolAddress((void**)&w1l, g_w1l);
    cudaGetSymbolAddress((void**)&w2h, g_w2h); cudaGetSymbolAddress((void**)&w2l, g_w2l);

    cudaFuncSetAttribute(gemm_tc<0, true>,  cudaFuncAttributeMaxDynamicSharedMemorySize, GSMEM);
    cudaFuncSetAttribute(gemm_tc<3, true>,  cudaFuncAttributeMaxDynamicSharedMemorySize, GSMEM);
    cudaFuncSetAttribute(gemm_tc<1, false>, cudaFuncAttributeMaxDynamicSharedMemorySize, GSMEM);
    cudaFuncSetAttribute(gemm_tc<2, false>, cudaFuncAttributeMaxDynamicSharedMemorySize, GSMEM);
    cudaFuncSetAttribute(attn_tc, cudaFuncAttributeMaxDynamicSharedMemorySize, ATT_SMEM);

    padcvt_x<<<(BN_ * SP * D) / 256, 256>>>(x, xph, xpl);
    wtall<<<1024, dim3(32, 8)>>>(Wq, Wk, Wv, Wo, W1, W2,
                                 wqh, wql, wkh, wkl, wvh, wvl,
                                 woh, wol, w1h, w1l, w2h, w2l);

    const dim3 gD(D / 128,  TOK / 128);
    const dim3 gF(Fd / 128, TOK / 128);
    const float qscale = 0.17677669529663687f;   // 1/sqrt(32)

    gemm_tc<3, true><<<gD, 256, GSMEM>>>(xph, xpl, D, wqh, wql, 3 * D, D, 3, 0, qscale,
                                         bq, nullptr, nullptr, qh, ql, D);
    gemm_tc<3, true><<<gD, 256, GSMEM>>>(xph, xpl, D, wkh, wkl, 3 * D, D, 3, 0, 1.f,
                                         bk, nullptr, nullptr, kh, kl, D);
    gemm_tc<0, true><<<gD, 256, GSMEM>>>(xph, xpl, D, wvh, wvl, D,     D, 1, 1, 1.f,
                                         bv, nullptr, v, nullptr, nullptr, D);
    attn_tc<<<Bd * S1 * Hh, 256, ATT_SMEM>>>(qh, ql, kh, kl, v, aoh, aol);
    gemm_tc<1, false><<<gD, 256, GSMEM>>>(aoh, aol, D, woh, wol, D, D, 1, 0, 1.f,
                                          bo, x, sb, nullptr, nullptr, D);
    ln_k<true><<<TOK / 8, 256>>>(sb, g1, be1, hbuf, hh, hl);
    gemm_tc<2, false><<<gF, 256, GSMEM>>>(hh, hl, D, w1h, w1l, D, D, 1, 0, 1.f,
                                          b1, nullptr, nullptr, ffh, ffl, Fd);
    gemm_tc<1, false><<<gD, 256, GSMEM>>>(ffh, ffl, Fd, w2h, w2l, Fd, Fd, 1, 0, 1.f,
                                          b2, hbuf, sb, nullptr, nullptr, D);
    ln_k<false><<<TOK / 8, 256>>>(sb, g2, be2, out, nullptr, nullptr);
}

// round 6
// speedup vs baseline: 2.8220x; 1.0082x over previous
#include <cuda_runtime.h>
#include <cuda_bf16.h>
#include <cstdint>
#include <math.h>

using bf16 = __nv_bfloat16;

// ---------------- problem constants ----------------
constexpr int Bd  = 4;
constexpr int S1  = 64;
constexpr int S2  = 256;
constexpr int D   = 256;
constexpr int Hh  = 8;
constexpr int HD  = 32;
constexpr int Fd  = 1024;
constexpr int TOK = Bd * S1 * S2;     // 65536
constexpr int BN_ = Bd * S1;          // 256
constexpr int SP  = S2 + 2;           // padded time length 258

// ---------------- scratch (device globals) ----------------
__device__ bf16  g_xph[BN_ * SP * D];
__device__ bf16  g_xpl[BN_ * SP * D];
__device__ bf16  g_qh [TOK * D];
__device__ bf16  g_ql [TOK * D];
__device__ bf16  g_kh [TOK * D];
__device__ bf16  g_kl [TOK * D];
__device__ float g_v  [TOK * D];
__device__ bf16  g_aoh[TOK * D];
__device__ bf16  g_aol[TOK * D];
__device__ float g_s  [TOK * D];
__device__ float g_h  [TOK * D];
__device__ bf16  g_hh [TOK * D];
__device__ bf16  g_hl [TOK * D];
__device__ bf16  g_ffh[TOK * Fd];
__device__ bf16  g_ffl[TOK * Fd];
// transposed weights, hi/lo
__device__ bf16 g_wqh[D * 3 * D], g_wql[D * 3 * D];
__device__ bf16 g_wkh[D * 3 * D], g_wkl[D * 3 * D];
__device__ bf16 g_wvh[D * D],     g_wvl[D * D];
__device__ bf16 g_woh[D * D],     g_wol[D * D];
__device__ bf16 g_w1h[Fd * D],    g_w1l[Fd * D];
__device__ bf16 g_w2h[D * Fd],    g_w2l[D * Fd];

// ---------------- helpers ----------------
__device__ __forceinline__ uint32_t smem_to_u32(const void* p) {
    uint32_t a;
    asm("{ .reg .u64 t; cvta.to.shared.u64 t, %1; cvt.u32.u64 %0, t; }" : "=r"(a) : "l"(p));
    return a;
}
#define CP_ASYNC16(s, g) \
    asm volatile("cp.async.cg.shared.global [%0], [%1], 16;" :: "r"((uint32_t)(s)), "l"(g))
#define CP_ASYNC_COMMIT() asm volatile("cp.async.commit_group;" ::: "memory")

__device__ __forceinline__ void ldsm4(uint32_t addr, uint32_t& r0, uint32_t& r1,
                                      uint32_t& r2, uint32_t& r3) {
    asm volatile("ldmatrix.sync.aligned.m8n8.x4.shared.b16 {%0,%1,%2,%3}, [%4];"
                 : "=r"(r0), "=r"(r1), "=r"(r2), "=r"(r3) : "r"(addr));
}
__device__ __forceinline__ void mma_bf16(float* c, const uint32_t* a, const uint32_t* b) {
    asm volatile("mma.sync.aligned.m16n8k16.row.col.f32.bf16.bf16.f32 "
                 "{%0,%1,%2,%3}, {%4,%5,%6,%7}, {%8,%9}, {%0,%1,%2,%3};"
                 : "+f"(c[0]), "+f"(c[1]), "+f"(c[2]), "+f"(c[3])
                 : "r"(a[0]), "r"(a[1]), "r"(a[2]), "r"(a[3]), "r"(b[0]), "r"(b[1]));
}
__device__ __forceinline__ void split_bf16(float v, bf16& h, bf16& l) {
    h = __float2bfloat16(v);
    l = __float2bfloat16(v - __bfloat162float(h));
}
__device__ __forceinline__ uint32_t pack2(bf16 a, bf16 b) {
    __nv_bfloat162 p; p.x = a; p.y = b;
    return *(uint32_t*)&p;
}
// 64B-row swizzle: 4 16B columns, rotate by (row>>1)&3 -> conflict-free ldsm + stores
__device__ __forceinline__ uint32_t sw64(int row, int c) {
    return (uint32_t)(row * 64 + ((c ^ ((row >> 1) & 3)) << 4));
}

// ---------------------------------------------------------------------------
// Tensor-core GEMM via mma.sync bf16, 128x128 block tile, BK=32, split-bf16
// (3 accumulating passes), cp.async 3-stage pipeline (single barrier per
// chunk, cutlass-style), 2 CTAs/SM. When launched with gridDim.z == 2,
// blockIdx.z selects the (B2, bias2, out2, scl2) set (used to fuse Q and K).
// smem stage (32KB): [Ah 8K][Al 8K][Bh 8K][Bl 8K]
// EPI: 0 = bias*scl -> fp32 ; 1 = bias*scl + R -> fp32 ;
//      2 = bias*scl + leaky -> bf16 hi/lo ; 3 = bias*scl -> bf16 hi/lo
// ---------------------------------------------------------------------------
constexpr int GSTAGE = 32768;
constexpr int GSMEM  = 3 * GSTAGE;   // 98304

template<int EPI, bool CONV>
__global__ __launch_bounds__(256, 2)
void gemm_tc(const bf16* __restrict__ Ah, const bf16* __restrict__ Al, int ldA,
             const bf16* Bh_, const bf16* Bl_, int ldB,
             int Ktap, int ntaps, int tapbase, float scl_,
             const float* bias_, const float* __restrict__ R,
             float* Cf_, bf16* Ch_, bf16* Cl_, int Nt,
             const bf16* Bh2, const bf16* Bl2, const float* bias2, float scl2,
             bf16* Ch2, bf16* Cl2)
{
    extern __shared__ char smem[];
    const uint32_t sbase = smem_to_u32(smem);
    const int tid = threadIdx.x, wid = tid >> 5, lane = tid & 31;
    const int m0 = blockIdx.y * 128, n0 = blockIdx.x * 128;

    const bf16* Bh = Bh_;  const bf16* Bl = Bl_;
    const float* bias = bias_;  float scl = scl_;
    float* Cf = Cf_;  bf16* Ch = Ch_;  bf16* Cl = Cl_;
    if (blockIdx.z == 1) {
        Bh = Bh2; Bl = Bl2; bias = bias2; scl = scl2; Ch = Ch2; Cl = Cl2;
    }

    int rowbase;
    if (CONV) { const int bn = m0 >> 8; const int t0 = m0 & 255; rowbase = bn * SP + t0 + tapbase; }
    else      { rowbase = m0; }

    const int kcpt = Ktap >> 5;          // 32-wide K chunks per tap
    const int nch  = ntaps * kcpt;
    const int c4   = tid & 3;            // 16B column 0..3
    const int rw0  = tid >> 2;           // row 0..63

    auto load_chunk = [&](int c, int stage) {
        const int tap = c / kcpt;
        const int kt  = (c - tap * kcpt) << 5;
        const size_t aoff = (size_t)(rowbase + tap) * ldA + kt + c4 * 8;
        const size_t boff = (size_t)n0 * ldB + (size_t)tap * Ktap + kt + c4 * 8;
        const uint32_t st = sbase + stage * GSTAGE;
#pragma unroll
        for (int i = 0; i < 2; i++) {
            const int row = rw0 + i * 64;
            const uint32_t so = sw64(row, c4);
            CP_ASYNC16(st +         so, Ah + aoff + (size_t)row * ldA);
            CP_ASYNC16(st +  8192 + so, Al + aoff + (size_t)row * ldA);
            CP_ASYNC16(st + 16384 + so, Bh + boff + (size_t)row * ldB);
            CP_ASYNC16(st + 24576 + so, Bl + boff + (size_t)row * ldB);
        }
        CP_ASYNC_COMMIT();
    };

    load_chunk(0, 0);
    load_chunk(1, 1);

    const int wm  = wid & 1,  wn  = wid >> 1;
    const int m0w = wm * 64,  n0w = wn * 32;
    const int tq  = lane >> 3, rin = lane & 7;
    const int aRow = m0w + (tq & 1) * 8 + rin;
    const int akh  = tq >> 1;
    const int bRow = n0w + (tq >> 1) * 8 + rin;
    const int bkh  = tq & 1;

    float acc[4][4][4];
#pragma unroll
    for (int i = 0; i < 4; i++)
#pragma unroll
        for (int j = 0; j < 4; j++)
#pragma unroll
            for (int r = 0; r < 4; r++) acc[i][j][r] = 0.f;

    for (int c = 0; c < nch; c++) {
        // chunk c must be complete: normally {c, c+1} outstanding -> wait 1;
        // at the final chunk only {c} is outstanding -> wait 0.
        if (c + 1 < nch) asm volatile("cp.async.wait_group 1;" ::: "memory");
        else             asm volatile("cp.async.wait_group 0;" ::: "memory");
        __syncthreads();
        // refill the slot consumed at iteration c-1 (barrier-protected)
        if (c + 2 < nch) load_chunk(c + 2, (c + 2) % 3);

        const uint32_t Ab = sbase + (c % 3) * GSTAGE;
        const uint32_t Bb = Ab + 16384;

#pragma unroll
        for (int ks = 0; ks < 2; ks++) {
            uint32_t ah[4][4], al[4][4], bh[4][2], bl[4][2];
#pragma unroll
            for (int mt = 0; mt < 4; mt++) {
                const int r = aRow + mt * 16;
                const uint32_t ad = Ab + sw64(r, ks * 2 + akh);
                ldsm4(ad,         ah[mt][0], ah[mt][1], ah[mt][2], ah[mt][3]);
                ldsm4(ad + 8192,  al[mt][0], al[mt][1], al[mt][2], al[mt][3]);
            }
#pragma unroll
            for (int nt2 = 0; nt2 < 2; nt2++) {
                const int r = bRow + nt2 * 16;
                const uint32_t bd = Bb + sw64(r, ks * 2 + bkh);
                uint32_t r0, r1, r2, r3;
                ldsm4(bd, r0, r1, r2, r3);
                bh[nt2 * 2][0] = r0; bh[nt2 * 2][1] = r1;
                bh[nt2 * 2 + 1][0] = r2; bh[nt2 * 2 + 1][1] = r3;
                ldsm4(bd + 8192, r0, r1, r2, r3);
                bl[nt2 * 2][0] = r0; bl[nt2 * 2][1] = r1;
                bl[nt2 * 2 + 1][0] = r2; bl[nt2 * 2 + 1][1] = r3;
            }
#pragma unroll
            for (int mt = 0; mt < 4; mt++)
#pragma unroll
                for (int nt = 0; nt < 4; nt++) {
                    mma_bf16(acc[mt][nt], ah[mt], bh[nt]);
                    mma_bf16(acc[mt][nt], ah[mt], bl[nt]);
                    mma_bf16(acc[mt][nt], al[mt], bh[nt]);
                }
        }
    }

    const int erow = lane >> 2;
    const int ecol = (lane & 3) * 2;
#pragma unroll
    for (int mt = 0; mt < 4; mt++) {
#pragma unroll
        for (int nt = 0; nt < 4; nt++) {
            const int col = n0 + n0w + nt * 8 + ecol;
            const float2 bi = *(const float2*)&bias[col];
#pragma unroll
            for (int half = 0; half < 2; half++) {
                const int row = m0 + m0w + mt * 16 + erow + half * 8;
                float v0 = (acc[mt][nt][half * 2 + 0] + bi.x) * scl;
                float v1 = (acc[mt][nt][half * 2 + 1] + bi.y) * scl;
                if (EPI == 1) {
                    const float2 rr = *(const float2*)&R[(size_t)row * Nt + col];
                    v0 += rr.x; v1 += rr.y;
                }
                if (EPI >= 2) {
                    if (EPI == 2) {
                        v0 = v0 > 0.f ? v0 : 0.01f * v0;
                        v1 = v1 > 0.f ? v1 : 0.01f * v1;
                    }
                    bf16 h0, l0, h1, l1;
                    split_bf16(v0, h0, l0); split_bf16(v1, h1, l1);
                    *(uint32_t*)&Ch[(size_t)row * Nt + col] = pack2(h0, h1);
                    *(uint32_t*)&Cl[(size_t)row * Nt + col] = pack2(l0, l1);
                } else {
                    float2 o; o.x = v0; o.y = v1;
                    *(float2*)&Cf[(size_t)row * Nt + col] = o;
                }
            }
        }
    }
}

// ---------------------------------------------------------------------------
// pad + split x into bf16 hi/lo padded buffer [bn][258][256]
// ---------------------------------------------------------------------------
__global__ __launch_bounds__(256)
void padcvt_x(const float* __restrict__ x, bf16* __restrict__ xh, bf16* __restrict__ xl)
{
    const size_t i = (size_t)blockIdx.x * 256 + threadIdx.x;
    const int d = (int)(i & 255);
    const size_t rest = i >> 8;
    const int t = (int)(rest % SP);
    const size_t bn = rest / SP;
    float v = 0.f;
    if (t >= 1 && t <= S2) v = x[(bn * S2 + (t - 1)) * D + d];
    bf16 h, l; split_bf16(v, h, l);
    xh[i] = h; xl[i] = l;
}

// ---------------------------------------------------------------------------
// fused weight transpose+split: 6 weights in one launch (1024 32x32 tiles)
// ---------------------------------------------------------------------------
__global__ __launch_bounds__(256)
void wtall(const float* __restrict__ Wq, const float* __restrict__ Wk,
           const float* __restrict__ Wv, const float* __restrict__ Wo,
           const float* __restrict__ W1, const float* __restrict__ W2,
           bf16* wqh, bf16* wql, bf16* wkh, bf16* wkl,
           bf16* wvh, bf16* wvl, bf16* woh, bf16* wol,
           bf16* w1h, bf16* w1l, bf16* w2h, bf16* w2l)
{
    __shared__ float ts[32][33];
    const int t = blockIdx.x;
    const float* W; bf16 *Bh, *Bl; int K, N, lt;
    if      (t < 192) { W = Wq; Bh = wqh; Bl = wql; K = 768;  N = 256;  lt = t; }
    else if (t < 384) { W = Wk; Bh = wkh; Bl = wkl; K = 768;  N = 256;  lt = t - 192; }
    else if (t < 448) { W = Wv; Bh = wvh; Bl = wvl; K = 256;  N = 256;  lt = t - 384; }
    else if (t < 512) { W = Wo; Bh = woh; Bl = wol; K = 256;  N = 256;  lt = t - 448; }
    else if (t < 768) { W = W1; Bh = w1h; Bl = w1l; K = 256;  N = 1024; lt = t - 512; }
    else              { W = W2; Bh = w2h; Bl = w2l; K = 1024; N = 256;  lt = t - 768; }
    const int ntn = N / 32;
    const int n0 = (lt % ntn) * 32, k0 = (lt / ntn) * 32;
    const int tx = threadIdx.x, ty = threadIdx.y;   // 32 x 8
#pragma unroll
    for (int j = 0; j < 4; j++)
        ts[ty + j * 8][tx] = W[(size_t)(k0 + ty + j * 8) * N + n0 + tx];
    __syncthreads();
#pragma unroll
    for (int j = 0; j < 4; j++) {
        const float v = ts[tx][ty + j * 8];
        bf16 h, l; split_bf16(v, h, l);
        const size_t o = (size_t)(n0 + ty + j * 8) * K + k0 + tx;
        Bh[o] = h; Bl[o] = l;
    }
}

// ---------------------------------------------------------------------------
// Flash attention on tensor cores. One block per (b,n,h); 8 warps x 32 rows.
// ---------------------------------------------------------------------------
constexpr int ATT_SMEM = 4 * 20480 + 2 * 16896;   // 115712

__global__ __launch_bounds__(256)
void attn_tc(const bf16* __restrict__ qh, const bf16* __restrict__ ql,
             const bf16* __restrict__ kh, const bf16* __restrict__ kl,
             const float* __restrict__ v,
             bf16* __restrict__ oh, bf16* __restrict__ ol)
{
    extern __shared__ char smem[];
    const uint32_t sb = smem_to_u32(smem);
    const uint32_t Qh = sb, Ql_ = sb + 20480, Kh = sb + 40960, Kl_ = sb + 61440;
    const uint32_t Vth = sb + 81920;
    bf16* vth_p = (bf16*)(smem + 81920);
    bf16* vtl_p = (bf16*)(smem + 98816);

    const int tid = threadIdx.x, wid = tid >> 5, lane = tid & 31;
    const int h = blockIdx.x & 7, bn = blockIdx.x >> 3;
    const size_t gbase = (size_t)bn * 256 * 256 + h * 32;

    for (int idx = tid; idx < 1024; idx += 256) {
        const int row = idx >> 2, c = idx & 3;
        const size_t g = gbase + (size_t)row * 256 + c * 8;
        const uint32_t so = row * 80 + c * 16;
        CP_ASYNC16(Qh  + so, qh + g);
        CP_ASYNC16(Ql_ + so, ql + g);
        CP_ASYNC16(Kh  + so, kh + g);
        CP_ASYNC16(Kl_ + so, kl + g);
    }
    CP_ASYNC_COMMIT();
    for (int idx = tid; idx < 2048; idx += 256) {
        const int row = idx >> 3, d4 = (idx & 7) * 4;
        const float4 vv = *(const float4*)&v[gbase + (size_t)row * 256 + d4];
        const float va[4] = { vv.x, vv.y, vv.z, vv.w };
#pragma unroll
        for (int i = 0; i < 4; i++) {
            bf16 hb, lb; split_bf16(va[i], hb, lb);
            vth_p[(d4 + i) * 264 + row] = hb;
            vtl_p[(d4 + i) * 264 + row] = lb;
        }
    }
    asm volatile("cp.async.wait_group 0;" ::: "memory");
    __syncthreads();

    const int tq = lane >> 3, rin = lane & 7;
    const int aR  = (tq & 1) * 8 + rin;
    const int akh = tq >> 1;
    const int bR  = (tq >> 1) * 8 + rin;
    const int bkh = tq & 1;

    uint32_t qfh[2][2][4], qfl[2][2][4];
#pragma unroll
    for (int mt = 0; mt < 2; mt++)
#pragma unroll
        for (int ks = 0; ks < 2; ks++) {
            const uint32_t ad = Qh + (uint32_t)((wid * 32 + mt * 16 + aR) * 80)
                              + (uint32_t)((ks * 2 + akh) * 16);
            ldsm4(ad,          qfh[mt][ks][0], qfh[mt][ks][1], qfh[mt][ks][2], qfh[mt][ks][3]);
            ldsm4(ad + 20480,  qfl[mt][ks][0], qfl[mt][ks][1], qfl[mt][ks][2], qfl[mt][ks][3]);
        }

    float O[2][4][4];
#pragma unroll
    for (int mt = 0; mt < 2; mt++)
#pragma unroll
        for (int j = 0; j < 4; j++)
#pragma unroll
            for (int r = 0; r < 4; r++) O[mt][j][r] = 0.f;
    float mrow[2][2] = { {-1e30f, -1e30f}, {-1e30f, -1e30f} };
    float lrow[2][2] = { {0.f, 0.f}, {0.f, 0.f} };

    for (int s0 = 0; s0 < 256; s0 += 64) {
        float acc[2][8][4];
#pragma unroll
        for (int mt = 0; mt < 2; mt++)
#pragma unroll
            for (int j = 0; j < 8; j++)
#pragma unroll
                for (int r = 0; r < 4; r++) acc[mt][j][r] = 0.f;

#pragma unroll
        for (int ks = 0; ks < 2; ks++) {
            uint32_t kbh[8][2], kbl[8][2];
#pragma unroll
            for (int g = 0; g < 4; g++) {
                const uint32_t kd = Kh + (uint32_t)((s0 + g * 16 + bR) * 80)
                                  + (uint32_t)((ks * 2 + bkh) * 16);
                uint32_t r0, r1, r2, r3;
                ldsm4(kd, r0, r1, r2, r3);
                kbh[g * 2][0] = r0; kbh[g * 2][1] = r1;
                kbh[g * 2 + 1][0] = r2; kbh[g * 2 + 1][1] = r3;
                ldsm4(kd + 20480, r0, r1, r2, r3);
                kbl[g * 2][0] = r0; kbl[g * 2][1] = r1;
                kbl[g * 2 + 1][0] = r2; kbl[g * 2 + 1][1] = r3;
            }
#pragma unroll
            for (int mt = 0; mt < 2; mt++)
#pragma unroll
                for (int j = 0; j < 8; j++) {
                    mma_bf16(acc[mt][j], qfh[mt][ks], kbh[j]);
                    mma_bf16(acc[mt][j], qfh[mt][ks], kbl[j]);
                    mma_bf16(acc[mt][j], qfl[mt][ks], kbh[j]);
                }
        }

#pragma unroll
        for (int mt = 0; mt < 2; mt++) {
            float mxA = -1e30f, mxB = -1e30f;
#pragma unroll
            for (int j = 0; j < 8; j++) {
                mxA = fmaxf(mxA, fmaxf(acc[mt][j][0], acc[mt][j][1]));
                mxB = fmaxf(mxB, fmaxf(acc[mt][j][2], acc[mt][j][3]));
            }
            mxA = fmaxf(mxA, __shfl_xor_sync(0xffffffffu, mxA, 1));
            mxA = fmaxf(mxA, __shfl_xor_sync(0xffffffffu, mxA, 2));
            mxB = fmaxf(mxB, __shfl_xor_sync(0xffffffffu, mxB, 1));
            mxB = fmaxf(mxB, __shfl_xor_sync(0xffffffffu, mxB, 2));
            const float mnA = fmaxf(mrow[mt][0], mxA);
            const float mnB = fmaxf(mrow[mt][1], mxB);
            const float fA = __expf(mrow[mt][0] - mnA);
            const float fB = __expf(mrow[mt][1] - mnB);
            mrow[mt][0] = mnA; mrow[mt][1] = mnB;
            float sA = 0.f, sB = 0.f;
#pragma unroll
            for (int j = 0; j < 8; j++) {
                acc[mt][j][0] = __expf(acc[mt][j][0] - mnA);
                acc[mt][j][1] = __expf(acc[mt][j][1] - mnA);
                acc[mt][j][2] = __expf(acc[mt][j][2] - mnB);
                acc[mt][j][3] = __expf(acc[mt][j][3] - mnB);
                sA += acc[mt][j][0] + acc[mt][j][1];
                sB += acc[mt][j][2] + acc[mt][j][3];
            }
            lrow[mt][0] = lrow[mt][0] * fA + sA;
            lrow[mt][1] = lrow[mt][1] * fB + sB;
#pragma unroll
            for (int j = 0; j < 4; j++) {
                O[mt][j][0] *= fA; O[mt][j][1] *= fA;
                O[mt][j][2] *= fB; O[mt][j][3] *= fB;
            }
        }

#pragma unroll
        for (int kt = 0; kt < 4; kt++) {
            uint32_t vbh[4][2], vbl[4][2];
#pragma unroll
            for (int g2 = 0; g2 < 2; g2++) {
                const uint32_t vd = Vth + (uint32_t)((g2 * 16 + bR) * 528)
                                  + (uint32_t)((s0 + kt * 16) * 2 + bkh * 16);
                uint32_t r0, r1, r2, r3;
                ldsm4(vd, r0, r1, r2, r3);
                vbh[g2 * 2][0] = r0; vbh[g2 * 2][1] = r1;
                vbh[g2 * 2 + 1][0] = r2; vbh[g2 * 2 + 1][1] = r3;
                ldsm4(vd + 16896, r0, r1, r2, r3);
                vbl[g2 * 2][0] = r0; vbl[g2 * 2][1] = r1;
                vbl[g2 * 2 + 1][0] = r2; vbl[g2 * 2 + 1][1] = r3;
            }
#pragma unroll
            for (int mt = 0; mt < 2; mt++) {
                uint32_t ph[4], pl[4];
#pragma unroll
                for (int half = 0; half < 2; half++) {
                    const int j = 2 * kt + half;
                    bf16 h0, l0, h1, l1, h2, l2, h3, l3;
                    split_bf16(acc[mt][j][0], h0, l0);
                    split_bf16(acc[mt][j][1], h1, l1);
                    split_bf16(acc[mt][j][2], h2, l2);
                    split_bf16(acc[mt][j][3], h3, l3);
                    ph[half * 2 + 0] = pack2(h0, h1);  pl[half * 2 + 0] = pack2(l0, l1);
                    ph[half * 2 + 1] = pack2(h2, h3);  pl[half * 2 + 1] = pack2(l2, l3);
                }
#pragma unroll
                for (int j2 = 0; j2 < 4; j2++) {
                    mma_bf16(O[mt][j2], ph, vbh[j2]);
                    mma_bf16(O[mt][j2], ph, vbl[j2]);
                    mma_bf16(O[mt][j2], pl, vbh[j2]);
                }
            }
        }
    }

#pragma unroll
    for (int mt = 0; mt < 2; mt++) {
        float lA = lrow[mt][0], lB = lrow[mt][1];
        lA += __shfl_xor_sync(0xffffffffu, lA, 1);
        lA += __shfl_xor_sync(0xffffffffu, lA, 2);
        lB += __shfl_xor_sync(0xffffffffu, lB, 1);
        lB += __shfl_xor_sync(0xffffffffu, lB, 2);
        const float invA = 1.f / lA, invB = 1.f / lB;
        const int rowA = wid * 32 + mt * 16 + (lane >> 2);
        const size_t gA = gbase + (size_t)rowA * 256;
        const size_t gB = gA + (size_t)8 * 256;
#pragma unroll
        for (int j2 = 0; j2 < 4; j2++) {
            const int col = j2 * 8 + (lane & 3) * 2;
            const float a0 = O[mt][j2][0] * invA, a1 = O[mt][j2][1] * invA;
            const float b0 = O[mt][j2][2] * invB, b1 = O[mt][j2][3] * invB;
            bf16 h0, l0, h1, l1;
            split_bf16(a0, h0, l0); split_bf16(a1, h1, l1);
            *(uint32_t*)&oh[gA + col] = pack2(h0, h1);
            *(uint32_t*)&ol[gA + col] = pack2(l0, l1);
            split_bf16(b0, h0, l0); split_bf16(b1, h1, l1);
            *(uint32_t*)&oh[gB + col] = pack2(h0, h1);
            *(uint32_t*)&ol[gB + col] = pack2(l0, l1);
        }
    }
}

// ---------------------------------------------------------------------------
// LayerNorm (D=256). Optionally emits bf16 hi/lo of the normalized output.
// ---------------------------------------------------------------------------
template<bool EMIT>
__global__ __launch_bounds__(256)
void ln_k(const float* __restrict__ X, const float* __restrict__ g,
          const float* __restrict__ be, float* __restrict__ Y,
          bf16* __restrict__ Yh, bf16* __restrict__ Yl)
{
    const int r    = blockIdx.x * 8 + (threadIdx.x >> 5);
    const int lane = threadIdx.x & 31;
    const float* xr = X + (long long)r * D;

    float xv[8];
    float s = 0.f, ss = 0.f;
#pragma unroll
    for (int j = 0; j < 8; j++) {
        const float t = xr[lane + j * 32];
        xv[j] = t; s += t; ss += t * t;
    }
#pragma unroll
    for (int ofs = 16; ofs > 0; ofs >>= 1) {
        s  += __shfl_xor_sync(0xffffffffu, s,  ofs);
        ss += __shfl_xor_sync(0xffffffffu, ss, ofs);
    }
    const float mu  = s * (1.f / 256.f);
    const float var = ss * (1.f / 256.f) - mu * mu;
    const float rs  = rsqrtf(var + 1e-5f);

#pragma unroll
    for (int j = 0; j < 8; j++) {
        const int d = lane + j * 32;
        const float y = (xv[j] - mu) * rs * g[d] + be[d];
        Y[(long long)r * D + d] = y;
        if (EMIT) {
            bf16 h, l; split_bf16(y, h, l);
            Yh[(long long)r * D + d] = h;
            Yl[(long long)r * D + d] = l;
        }
    }
}

// ---------------------------------------------------------------------------
extern "C" void kernel_launch(void* const* d_in, const int* in_sizes, int n_in,
                              void* d_out, int out_size)
{
    const float* x   = (const float*)d_in[0];
    const float* Wq  = (const float*)d_in[1];
    const float* bq  = (const float*)d_in[2];
    const float* Wk  = (const float*)d_in[3];
    const float* bk  = (const float*)d_in[4];
    const float* Wv  = (const float*)d_in[5];
    const float* bv  = (const float*)d_in[6];
    const float* Wo  = (const float*)d_in[7];
    const float* bo  = (const float*)d_in[8];
    const float* W1  = (const float*)d_in[9];
    const float* b1  = (const float*)d_in[10];
    const float* W2  = (const float*)d_in[11];
    const float* b2  = (const float*)d_in[12];
    const float* g1  = (const float*)d_in[13];
    const float* be1 = (const float*)d_in[14];
    const float* g2  = (const float*)d_in[15];
    const float* be2 = (const float*)d_in[16];
    float* out = (float*)d_out;

    bf16 *xph, *xpl, *qh, *ql, *kh, *kl, *aoh, *aol, *hh, *hl, *ffh, *ffl;
    bf16 *wqh, *wql, *wkh, *wkl, *wvh, *wvl, *woh, *wol, *w1h, *w1l, *w2h, *w2l;
    float *v, *sb, *hbuf;
    cudaGetSymbolAddress((void**)&xph, g_xph); cudaGetSymbolAddress((void**)&xpl, g_xpl);
    cudaGetSymbolAddress((void**)&qh,  g_qh);  cudaGetSymbolAddress((void**)&ql,  g_ql);
    cudaGetSymbolAddress((void**)&kh,  g_kh);  cudaGetSymbolAddress((void**)&kl,  g_kl);
    cudaGetSymbolAddress((void**)&v,   g_v);
    cudaGetSymbolAddress((void**)&aoh, g_aoh); cudaGetSymbolAddress((void**)&aol, g_aol);
    cudaGetSymbolAddress((void**)&sb,  g_s);   cudaGetSymbolAddress((void**)&hbuf, g_h);
    cudaGetSymbolAddress((void**)&hh,  g_hh);  cudaGetSymbolAddress((void**)&hl,  g_hl);
    cudaGetSymbolAddress((void**)&ffh, g_ffh); cudaGetSymbolAddress((void**)&ffl, g_ffl);
    cudaGetSymbolAddress((void**)&wqh, g_wqh); cudaGetSymbolAddress((void**)&wql, g_wql);
    cudaGetSymbolAddress((void**)&wkh, g_wkh); cudaGetSymbolAddress((void**)&wkl, g_wkl);
    cudaGetSymbolAddress((void**)&wvh, g_wvh); cudaGetSymbolAddress((void**)&wvl, g_wvl);
    cudaGetSymbolAddress((void**)&woh, g_woh); cudaGetSymbolAddress((void**)&wol, g_wol);
    cudaGetSymbolAddress((void**)&w1h, g_w1h); cudaGetSymbolAddress((void**)&w1l, g_w1l);
    cudaGetSymbolAddress((void**)&w2h, g_w2h); cudaGetSymbolAddress((void**)&w2l, g_w2l);

    cudaFuncSetAttribute(gemm_tc<0, true>,  cudaFuncAttributeMaxDynamicSharedMemorySize, GSMEM);
    cudaFuncSetAttribute(gemm_tc<3, true>,  cudaFuncAttributeMaxDynamicSharedMemorySize, GSMEM);
    cudaFuncSetAttribute(gemm_tc<1, false>, cudaFuncAttributeMaxDynamicSharedMemorySize, GSMEM);
    cudaFuncSetAttribute(gemm_tc<2, false>, cudaFuncAttributeMaxDynamicSharedMemorySize, GSMEM);
    cudaFuncSetAttribute(attn_tc, cudaFuncAttributeMaxDynamicSharedMemorySize, ATT_SMEM);

    padcvt_x<<<(BN_ * SP * D) / 256, 256>>>(x, xph, xpl);
    wtall<<<1024, dim3(32, 8)>>>(Wq, Wk, Wv, Wo, W1, W2,
                                 wqh, wql, wkh, wkl, wvh, wvl,
                                 woh, wol, w1h, w1l, w2h, w2l);

    const dim3 gQK(D / 128, TOK / 128, 2);   // fused Q (z=0) + K (z=1)
    const dim3 gD (D / 128, TOK / 128);
    const dim3 gF (Fd / 128, TOK / 128);
    const float qscale = 0.17677669529663687f;   // 1/sqrt(32)

    // fused Q+K (3-tap conv; bf16 hi/lo out; Q pre-scaled)
    gemm_tc<3, true><<<gQK, 256, GSMEM>>>(xph, xpl, D, wqh, wql, 3 * D, D, 3, 0, qscale,
                                          bq, nullptr, nullptr, qh, ql, D,
                                          wkh, wkl, bk, 1.f, kh, kl);
    gemm_tc<0, true><<<gD, 256, GSMEM>>>(xph, xpl, D, wvh, wvl, D, D, 1, 1, 1.f,
                                         bv, nullptr, v, nullptr, nullptr, D,
                                         nullptr, nullptr, nullptr, 0.f, nullptr, nullptr);
    attn_tc<<<Bd * S1 * Hh, 256, ATT_SMEM>>>(qh, ql, kh, kl, v, aoh, aol);
    gemm_tc<1, false><<<gD, 256, GSMEM>>>(aoh, aol, D, woh, wol, D, D, 1, 0, 1.f,
                                          bo, x, sb, nullptr, nullptr, D,
                                          nullptr, nullptr, nullptr, 0.f, nullptr, nullptr);
    ln_k<true><<<TOK / 8, 256>>>(sb, g1, be1, hbuf, hh, hl);
    gemm_tc<2, false><<<gF, 256, GSMEM>>>(hh, hl, D, w1h, w1l, D, D, 1, 0, 1.f,
                                          b1, nullptr, nullptr, ffh, ffl, Fd,
                                          nullptr, nullptr, nullptr, 0.f, nullptr, nullptr);
    gemm_tc<1, false><<<gD, 256, GSMEM>>>(ffh, ffl, Fd, w2h, w2l, Fd, Fd, 1, 0, 1.f,
                                          b2, hbuf, sb, nullptr, nullptr, D,
                                          nullptr, nullptr, nullptr, 0.f, nullptr, nullptr);
    ln_k<false><<<TOK / 8, 256>>>(sb, g2, be2, out, nullptr, nullptr);
}